// round 11
// baseline (speedup 1.0000x reference)
#include <cuda_runtime.h>
#include <math.h>

#define NAg 8
#define Hdim 64
#define LATENT 512
#define NACT 14
#define BSZ 4096
#define NROWS 32768   // BSZ*NAg
#define LN0002 (-6.2146080984221914f)

typedef unsigned long long u64;

// ---- packed fp32x2 helpers ----
__device__ __forceinline__ u64 bc2(float x) {
    u64 r; asm("mov.b64 %0, {%1, %2};" : "=l"(r) : "f"(x), "f"(x)); return r;
}
__device__ __forceinline__ void fma2(u64& d, u64 a, u64 b) {
    asm("fma.rn.f32x2 %0, %1, %2, %3;" : "=l"(d) : "l"(a), "l"(b), "l"(d));
}
__device__ __forceinline__ float2 up2(u64 v) {
    float lo, hi; asm("mov.b64 {%0, %1}, %2;" : "=f"(lo), "=f"(hi) : "l"(v));
    return make_float2(lo, hi);
}
__device__ __forceinline__ u64 lds2(const float* p) { return *(const u64*)p; }
__device__ __forceinline__ float tanh_fast(float x) {
    float r; asm("tanh.approx.f32 %0, %1;" : "=f"(r) : "f"(x)); return r;
}
__device__ __forceinline__ float sigmoid_fast(float x) {
    return 1.f / (1.f + __expf(-x));
}

// ---------------- scratch ----------------
__device__ float g_uae[NROWS * 128];
__device__ float g_ae_acc[2 * 128];
__device__ float g_mean[NROWS * 512];
__device__ float g_lvar[NROWS * 512];
__device__ float g_aw[NROWS * 512];
__device__ float g_L[NROWS * 128];
__device__ float g_R[NROWS * 128];
__device__ float g_in_acc[5 * 128];
__device__ float g_wqkv[64 * 384];

__global__ void k_zero() {
    int i = threadIdx.x;
    if (i < 256) g_ae_acc[i] = 0.f;
    if (i < 640) g_in_acc[i] = 0.f;
}

// ---------------- kernel A: fused mlp1 + GRU (512 thr, fast activations) ----------------
__global__ __launch_bounds__(512) void k_mlp1_gru(
    const float* __restrict__ in, const float* __restrict__ hin,
    const float* __restrict__ W1, const float* __restrict__ b1,
    const float* __restrict__ Wih, const float* __restrict__ bih,
    const float* __restrict__ Whh, const float* __restrict__ bhh,
    float* __restrict__ hout)
{
    __shared__ float sInT[96][34];
    __shared__ float sXT[64][34];
    __shared__ float sHT[64][34];
    int tid = threadIdx.x;
    int row0 = blockIdx.x * 32;

    for (int idx = tid; idx < 32 * 96; idx += 512) {
        int r = idx / 96, k = idx % 96;
        sInT[k][r] = in[(row0 + r) * 96 + k];
    }
    for (int idx = tid; idx < 32 * 64; idx += 512) {
        int r = idx / 64, k = idx % 64;
        sHT[k][r] = hin[(row0 + r) * 64 + k];
    }
    __syncthreads();

    int c = tid & 63;
    int rg = tid >> 6;      // 0..7 -> rows rg*4..+3
    {
        u64 acc2[2] = {0ull, 0ull};
        for (int k = 0; k < 96; k++) {
            u64 w2 = bc2(W1[k * 64 + c]);
#pragma unroll
            for (int t = 0; t < 2; t++)
                fma2(acc2[t], lds2(&sInT[k][rg * 4 + 2 * t]), w2);
        }
        float b = b1[c];
#pragma unroll
        for (int t = 0; t < 2; t++) {
            float2 v = up2(acc2[t]);
            v.x += b; v.y += b;
            v.x = v.x > 0.f ? v.x : 0.f;
            v.y = v.y > 0.f ? v.y : 0.f;
            *(float2*)&sXT[c][rg * 4 + 2 * t] = v;
        }
    }
    __syncthreads();

    {
        int j = c;
        u64 axr2[2], axz2[2], axn2[2], ahr2[2], ahz2[2], ahn2[2];
#pragma unroll
        for (int t = 0; t < 2; t++) { axr2[t]=axz2[t]=axn2[t]=ahr2[t]=ahz2[t]=ahn2[t]=0ull; }
        for (int k = 0; k < 64; k++) {
            u64 wr = bc2(Wih[k * 192 + j]);
            u64 wz = bc2(Wih[k * 192 + 64 + j]);
            u64 wn = bc2(Wih[k * 192 + 128 + j]);
            u64 vr = bc2(Whh[k * 192 + j]);
            u64 vz = bc2(Whh[k * 192 + 64 + j]);
            u64 vn = bc2(Whh[k * 192 + 128 + j]);
#pragma unroll
            for (int t = 0; t < 2; t++) {
                u64 x2 = lds2(&sXT[k][rg * 4 + 2 * t]);
                u64 h2 = lds2(&sHT[k][rg * 4 + 2 * t]);
                fma2(axr2[t], x2, wr); fma2(axz2[t], x2, wz); fma2(axn2[t], x2, wn);
                fma2(ahr2[t], h2, vr); fma2(ahz2[t], h2, vz); fma2(ahn2[t], h2, vn);
            }
        }
        float br = bih[j], bz = bih[64 + j], bn_ = bih[128 + j];
        float cr = bhh[j], cz = bhh[64 + j], cn = bhh[128 + j];
#pragma unroll
        for (int t = 0; t < 2; t++) {
            float2 xr = up2(axr2[t]), xz = up2(axz2[t]), xn = up2(axn2[t]);
            float2 hr = up2(ahr2[t]), hz = up2(ahz2[t]), hn = up2(ahn2[t]);
#pragma unroll
            for (int lz = 0; lz < 2; lz++) {
                int r = rg * 4 + 2 * t + lz;
                float XR = lz ? xr.y : xr.x, XZ = lz ? xz.y : xz.x, XN = lz ? xn.y : xn.x;
                float HR = lz ? hr.y : hr.x, HZ = lz ? hz.y : hz.x, HN = lz ? hn.y : hn.x;
                float rg_ = sigmoid_fast((XR + br) + (HR + cr));
                float zg  = sigmoid_fast((XZ + bz) + (HZ + cz));
                float ng  = tanh_fast((XN + bn_) + rg_ * (HN + cn));
                float hprev = sHT[j][r];
                hout[(row0 + r) * 64 + j] = (1.f - zg) * ng + zg * hprev;
            }
        }
    }
}

// ---------------- kernel B: ae1 GEMM + column stats (R8 form) ----------------
__global__ void k_ae1(const float* __restrict__ hsrc,
                      const float* __restrict__ Wae1, const float* __restrict__ bae1)
{
    __shared__ float sHT[64][34];
    __shared__ float sred[256];
    int tid = threadIdx.x;
    int row0 = blockIdx.x * 32;
    for (int idx = tid; idx < 32 * 64; idx += 256) {
        int r = idx / 64, k = idx % 64;
        sHT[k][r] = hsrc[(row0 + r) * 64 + k];
    }
    __syncthreads();
    int c = tid & 127;
    int rg = tid >> 7;
    u64 acc2[8];
#pragma unroll
    for (int t = 0; t < 8; t++) acc2[t] = 0ull;
    for (int k = 0; k < 64; k++) {
        u64 w2 = bc2(Wae1[k * 128 + c]);
#pragma unroll
        for (int t = 0; t < 8; t++)
            fma2(acc2[t], lds2(&sHT[k][rg * 16 + 2 * t]), w2);
    }
    float b = bae1[c];
    float s = 0.f, q = 0.f;
#pragma unroll
    for (int t = 0; t < 8; t++) {
        float2 u2 = up2(acc2[t]);
        float u0 = u2.x + b, u1 = u2.y + b;
        g_uae[(row0 + rg * 16 + 2 * t) * 128 + c] = u0;
        g_uae[(row0 + rg * 16 + 2 * t + 1) * 128 + c] = u1;
        s += u0 + u1; q += u0 * u0 + u1 * u1;
    }
    sred[tid] = s; __syncthreads();
    if (tid < 128) atomicAdd(&g_ae_acc[tid], sred[tid] + sred[tid + 128]);
    __syncthreads();
    sred[tid] = q; __syncthreads();
    if (tid < 128) atomicAdd(&g_ae_acc[128 + tid], sred[tid] + sred[tid + 128]);
}

// ---------------- kernel D: ae2 GEMM (R10 form: transposed sUT) ----------------
__global__ __launch_bounds__(256) void k_ae2(
    const float* __restrict__ Wae2, const float* __restrict__ bae2,
    const float* __restrict__ noise,
    const float* __restrict__ gae, const float* __restrict__ beae)
{
    __shared__ float sUT[128 * 34];
    __shared__ float s_sc[128], s_sh[128];
    int tid = threadIdx.x;
    int row0 = blockIdx.x * 32;
    int p = blockIdx.y;

    if (tid < 128) {
        float m = g_ae_acc[tid] * (1.f / 32768.f);
        float var = g_ae_acc[128 + tid] * (1.f / 32768.f) - m * m;
        float s = rsqrtf(var + 1e-5f) * gae[tid];
        s_sc[tid] = s;
        s_sh[tid] = beae[tid] - m * s;
    }
    __syncthreads();

    for (int idx = tid; idx < 32 * 128; idx += 256) {
        int r = idx >> 7, k = idx & 127;
        float u = g_uae[(size_t)row0 * 128 + idx];
        float v = u * s_sc[k] + s_sh[k];
        sUT[k * 34 + r] = v >= 0.f ? v : 0.01f * v;
    }
    __syncthreads();

    int rg = tid >> 5;
    int cg = tid & 31;
    int cm = p * 128 + cg * 4;
    int cv = 512 + cm;
    u64 acc2[2][8];
#pragma unroll
    for (int t = 0; t < 2; t++)
#pragma unroll
        for (int c = 0; c < 8; c++) acc2[t][c] = 0ull;

    for (int k = 0; k < 128; k++) {
        float4 wm = *(const float4*)&Wae2[k * 1024 + cm];
        float4 wv = *(const float4*)&Wae2[k * 1024 + cv];
        u64 wb[8];
        wb[0] = bc2(wm.x); wb[1] = bc2(wm.y); wb[2] = bc2(wm.z); wb[3] = bc2(wm.w);
        wb[4] = bc2(wv.x); wb[5] = bc2(wv.y); wb[6] = bc2(wv.z); wb[7] = bc2(wv.w);
#pragma unroll
        for (int t = 0; t < 2; t++) {
            u64 u2 = lds2(&sUT[k * 34 + rg * 4 + 2 * t]);
#pragma unroll
            for (int c = 0; c < 8; c++) fma2(acc2[t][c], u2, wb[c]);
        }
    }
    float4 bm = *(const float4*)&bae2[cm];
    float4 bv = *(const float4*)&bae2[cv];
#pragma unroll
    for (int t = 0; t < 2; t++) {
        float2 c0 = up2(acc2[t][0]), c1 = up2(acc2[t][1]);
        float2 c2 = up2(acc2[t][2]), c3 = up2(acc2[t][3]);
        float2 v0 = up2(acc2[t][4]), v1 = up2(acc2[t][5]);
        float2 v2 = up2(acc2[t][6]), v3 = up2(acc2[t][7]);
#pragma unroll
        for (int lz = 0; lz < 2; lz++) {
            size_t row = row0 + rg * 4 + 2 * t + lz;
            float m0 = (lz ? c0.y : c0.x) + bm.x;
            float m1 = (lz ? c1.y : c1.x) + bm.y;
            float m2 = (lz ? c2.y : c2.x) + bm.z;
            float m3 = (lz ? c3.y : c3.x) + bm.w;
            float l0 = fmaxf((lz ? v0.y : v0.x) + bv.x, LN0002);
            float l1 = fmaxf((lz ? v1.y : v1.x) + bv.y, LN0002);
            float l2 = fmaxf((lz ? v2.y : v2.x) + bv.z, LN0002);
            float l3 = fmaxf((lz ? v3.y : v3.x) + bv.w, LN0002);
            size_t off = row * 512 + cm;
            float4 nz = *(const float4*)&noise[off];
            *(float4*)&g_mean[off] = make_float4(m0, m1, m2, m3);
            *(float4*)&g_lvar[off] = make_float4(l0, l1, l2, l3);
            *(float4*)&g_aw[off]   = make_float4(m0 + __expf(0.5f * l0) * nz.x,
                                                 m1 + __expf(0.5f * l1) * nz.y,
                                                 m2 + __expf(0.5f * l2) * nz.z,
                                                 m3 + __expf(0.5f * l3) * nz.w);
        }
    }
}

// ---------------- kernel F: L/R GEMMs + column stats (R8 form) ----------------
__global__ void k_LR(const float* __restrict__ hsrc, const float* __restrict__ Win1)
{
    __shared__ float sHT[64][34];
    int tid = threadIdx.x;
    int row0 = blockIdx.x * 32;
    for (int idx = tid; idx < 32 * 64; idx += 256) {
        int r = idx / 64, k = idx % 64;
        sHT[k][r] = hsrc[(row0 + r) * 64 + k];
    }
    __syncthreads();
    int cc = tid;
    int cm = cc & 127;
    u64 acc2[16];
#pragma unroll
    for (int t = 0; t < 16; t++) acc2[t] = 0ull;
    for (int k = 0; k < 64; k++) {
        float w = (cc < 128) ? Win1[k * 128 + cm] : Win1[(64 + k) * 128 + cm];
        u64 w2 = bc2(w);
#pragma unroll
        for (int t = 0; t < 16; t++)
            fma2(acc2[t], lds2(&sHT[k][2 * t]), w2);
    }
    float* dst = (cc < 128) ? g_L : g_R;
    float s = 0.f, q = 0.f;
#pragma unroll
    for (int t = 0; t < 16; t++) {
        float2 v2 = up2(acc2[t]);
        dst[(row0 + 2 * t) * 128 + cm] = v2.x;
        dst[(row0 + 2 * t + 1) * 128 + cm] = v2.y;
        s += v2.x + v2.y; q += v2.x * v2.x + v2.y * v2.y;
    }
    atomicAdd(&g_in_acc[cc], s);
    atomicAdd(&g_in_acc[256 + cc], q);
}

__global__ void k_cross() {
    __shared__ float sred[256];
    int tid = threadIdx.x;
    int c = tid & 127;
    int bg = tid >> 7;
    int b0 = blockIdx.x * 32;
    float cr = 0.f;
    for (int bb = bg * 16; bb < bg * 16 + 16; bb++) {
        int b = b0 + bb;
        float sl = 0.f, sr = 0.f;
#pragma unroll
        for (int i = 0; i < 8; i++) {
            sl += g_L[(b * 8 + i) * 128 + c];
            sr += g_R[(b * 8 + i) * 128 + c];
        }
        cr += sl * sr;
    }
    sred[tid] = cr; __syncthreads();
    if (tid < 128) atomicAdd(&g_in_acc[512 + tid], sred[tid] + sred[tid + 128]);
}

// ---------------- kernel I: infer GEMM + KLD ----------------
__global__ __launch_bounds__(256) void k_infer(
    const float* __restrict__ Win2, const float* __restrict__ bin2,
    const float* __restrict__ bin1,
    const float* __restrict__ gin, const float* __restrict__ bein,
    float* __restrict__ kld_out)
{
    __shared__ float sL[8 * 128], sR[8 * 128];
    __shared__ float sU[32 * 128];
    __shared__ float sIP[32 * 128];
    __shared__ float s_sc[128], s_sh[128];
    __shared__ float sred[256];
    int b = blockIdx.x;
    int tid = threadIdx.x;
    for (int idx = tid; idx < 1024; idx += 256) {
        sL[idx] = g_L[(size_t)b * 1024 + idx];
        sR[idx] = g_R[(size_t)b * 1024 + idx];
    }
    if (tid < 128) {
        int c = tid;
        float sl = g_in_acc[c], sr = g_in_acc[128 + c];
        float ql = g_in_acc[256 + c], qr = g_in_acc[384 + c];
        float cr = g_in_acc[512 + c];
        float beta = bin1[c];
        const float Nr = 262144.f;
        float mean = 8.f * (sl + sr) / Nr + beta;
        float e2 = (8.f * ql + 8.f * qr + 2.f * cr + 16.f * beta * (sl + sr)) / Nr + beta * beta;
        float var = e2 - mean * mean;
        float s = rsqrtf(var + 1e-5f) * gin[c];
        s_sc[c] = s;
        s_sh[c] = bein[c] + (beta - mean) * s;
    }
    __syncthreads();

    int wr = tid >> 5;
    int cg = tid & 31;
    float4 bia = *(const float4*)&bin2[cg * 4];
    float kacc = 0.f;

    for (int half = 0; half < 2; half++) {
        int i0 = half * 4;
        for (int idx = tid; idx < 4096; idx += 256) {
            int r = idx >> 7, k = idx & 127;
            int ii = r >> 3, j = r & 7;
            float v = (sL[(i0 + ii) * 128 + k] + sR[j * 128 + k]) * s_sc[k] + s_sh[k];
            sU[idx] = v >= 0.f ? v : 0.01f * v;
        }
        __syncthreads();
        u64 acc2[4][2];
#pragma unroll
        for (int i = 0; i < 4; i++) { acc2[i][0] = 0ull; acc2[i][1] = 0ull; }
        for (int k = 0; k < 128; k++) {
            ulonglong2 w = *(const ulonglong2*)&Win2[k * 128 + cg * 4];
#pragma unroll
            for (int i = 0; i < 4; i++) {
                u64 u2 = bc2(sU[(wr * 4 + i) * 128 + k]);
                fma2(acc2[i][0], u2, w.x); fma2(acc2[i][1], u2, w.y);
            }
        }
#pragma unroll
        for (int i = 0; i < 4; i++) {
            float2 a01 = up2(acc2[i][0]), a23 = up2(acc2[i][1]);
            *(float4*)&sIP[(wr * 4 + i) * 128 + cg * 4] =
                make_float4(a01.x + bia.x, a01.y + bia.y, a23.x + bia.z, a23.y + bia.w);
        }
        __syncthreads();
        for (int ii = 0; ii < 4; ii++) {
            const float* mrow = g_mean + (size_t)(b * 8 + i0 + ii) * 512;
            const float* vrow = g_lvar + (size_t)(b * 8 + i0 + ii) * 512;
            for (int idx = tid; idx < 512; idx += 256) {
                int j = idx >> 6, d = idx & 63;
                float im  = sIP[(ii * 8 + j) * 128 + d];
                float liv = fmaxf(sIP[(ii * 8 + j) * 128 + 64 + d], LN0002);
                float riv = __expf(-liv);
                float lv  = vrow[idx];
                float v0  = __expf(lv);
                float dm  = mrow[idx] - im;
                kacc += 0.5f * (liv - lv) + 0.5f * (v0 + dm * dm) * riv - 0.5f;
            }
        }
        __syncthreads();
    }
    sred[tid] = kacc; __syncthreads();
    for (int s = 128; s > 0; s >>= 1) {
        if (tid < s) sred[tid] += sred[tid + s];
        __syncthreads();
    }
    if (tid == 0) kld_out[b] = sred[0] * (1.f / 4096.f);
}

__global__ void k_pack(const float* __restrict__ wq, const float* __restrict__ wk,
                       const float* __restrict__ wv)
{
    int idx = blockIdx.x * 256 + threadIdx.x;
    if (idx >= 64 * 384) return;
    int k = idx / 384, c = idx % 384;
    float v = (c < 128) ? wq[k * 128 + c] : (c < 256) ? wk[k * 128 + c - 128] : wv[k * 128 + c - 256];
    g_wqkv[idx] = v;
}

// ---------------- kernel K: fused MHA + layernorm + mlp2 -> qout ----------------
// Smem budget unchanged (91KB, 2 CTA/SM). After scores/PV, the dead Q/K/V
// regions are reused for W2 (8064 fl) + the 4 h rows (256 fl).
#define QPS 133
#define VPS 144
#define OPS 132
#define FPS 67
#define OFF_A   0
#define OFF_Q   2048
#define OFF_K   6304
#define OFF_V   10560
#define OFF_P   15168
#define OFF_O   16320
#define OFF_F   20544
#define OFF_MU  22688
#define OFF_RS  22720
#define OFF_W2  OFF_Q            // 2048 .. 10112 (8064 floats)
#define OFF_H   (OFF_Q + 8064)   // 10112 .. 10368 (256 floats)
#define ATTN_SMEM_FLOATS 22752

__global__ __launch_bounds__(512) void k_attn(
    const float* __restrict__ hsrc,
    const float* __restrict__ wfc,
    const float* __restrict__ gln, const float* __restrict__ bln,
    const float* __restrict__ W2, const float* __restrict__ b2,
    float* __restrict__ qout)
{
    extern __shared__ float sm[];
    float* sA  = sm + OFF_A;
    float* sQp = sm + OFF_Q;
    float* sKp = sm + OFF_K;
    float* sVp = sm + OFF_V;
    float* sP  = sm + OFF_P;
    float* sO  = sm + OFF_O;
    float* sF  = sm + OFF_F;
    float* sMu = sm + OFF_MU;
    float* sRs = sm + OFF_RS;
    float* sW2 = sm + OFF_W2;
    float* sH  = sm + OFF_H;

    int tid = threadIdx.x;
    int w = tid >> 5;
    int lane = tid & 31;

    size_t base = (size_t)blockIdx.x * 2048;
    for (int idx = tid; idx < 2048; idx += 512) sA[idx] = g_aw[base + idx];
    __syncthreads();

    // ---- QKV projections ----
    {
        int r0 = w * 2, r1 = r0 + 1;
        int cl = lane * 4;
        int h = cl >> 5, within = cl & 31;
        const float* ar0 = sA + r0 * 64;
        const float* ar1 = sA + r1 * 64;
#pragma unroll
        for (int pass = 0; pass < 3; pass++) {
            u64 a0p[2] = {0ull, 0ull}, a1p[2] = {0ull, 0ull};
            const float* wp = g_wqkv + pass * 128 + cl;
#pragma unroll 4
            for (int k = 0; k < 64; k++) {
                ulonglong2 w4 = *(const ulonglong2*)&wp[k * 384];
                u64 a0 = bc2(ar0[k]), a1 = bc2(ar1[k]);
                fma2(a0p[0], a0, w4.x); fma2(a0p[1], a0, w4.y);
                fma2(a1p[0], a1, w4.x); fma2(a1p[1], a1, w4.y);
            }
            float2 q001 = up2(a0p[0]), q023 = up2(a0p[1]);
            float2 q101 = up2(a1p[0]), q123 = up2(a1p[1]);
            if (pass < 2) {
                float* dst = (pass == 0) ? sQp : sKp;
                int pc = h * 33 + within;
                dst[r0 * QPS + pc]     = q001.x; dst[r0 * QPS + pc + 1] = q001.y;
                dst[r0 * QPS + pc + 2] = q023.x; dst[r0 * QPS + pc + 3] = q023.y;
                dst[r1 * QPS + pc]     = q101.x; dst[r1 * QPS + pc + 1] = q101.y;
                dst[r1 * QPS + pc + 2] = q123.x; dst[r1 * QPS + pc + 3] = q123.y;
            } else {
                int pc = h * 36 + within;
                *(float4*)&sVp[r0 * VPS + pc] = make_float4(q001.x, q001.y, q023.x, q023.y);
                *(float4*)&sVp[r1 * VPS + pc] = make_float4(q101.x, q101.y, q123.x, q123.y);
            }
        }
    }
    __syncthreads();

    // ---- scores + softmax ----
    {
        int b = w >> 2, h = w & 3;
        int s = lane & 7, dgrp = lane >> 3;
        const float* qb = sQp + (b * 8 + s) * QPS + h * 33 + dgrp * 8;
        float q[8];
#pragma unroll
        for (int d = 0; d < 8; d++) q[d] = qb[d];
        float scv[8];
#pragma unroll
        for (int u = 0; u < 8; u++) {
            const float* kr = sKp + (b * 8 + u) * QPS + h * 33 + dgrp * 8;
            float p = 0.f;
#pragma unroll
            for (int d = 0; d < 8; d++) p += q[d] * kr[d];
            scv[u] = p;
        }
#pragma unroll
        for (int u = 0; u < 8; u++) {
            scv[u] += __shfl_xor_sync(0xffffffffu, scv[u], 8);
            scv[u] += __shfl_xor_sync(0xffffffffu, scv[u], 16);
        }
        if (lane < 8) {
            float mx = -1e30f;
#pragma unroll
            for (int u = 0; u < 8; u++) {
                scv[u] *= 0.17677669529663687f;
                mx = fmaxf(mx, scv[u]);
            }
            float sum = 0.f;
#pragma unroll
            for (int u = 0; u < 8; u++) { scv[u] = __expf(scv[u] - mx); sum += scv[u]; }
            float inv = 1.f / sum;
            float* pr = sP + ((b * 4 + h) * 8 + s) * 9;
#pragma unroll
            for (int u = 0; u < 8; u++) pr[u] = scv[u] * inv;
        }
    }
    __syncthreads();

    // ---- O = P @ V ----
    {
        int b = w >> 2;
        int s0 = (w & 3) * 2, s1 = s0 + 1;
        int c0 = lane * 4;
        int h = c0 >> 5;
        int pc = h * 36 + (c0 & 31);
        float o0[4], o1[4];
#pragma unroll
        for (int t = 0; t < 4; t++) { o0[t] = 0.f; o1[t] = 0.f; }
#pragma unroll
        for (int u = 0; u < 8; u++) {
            float4 v4 = *(const float4*)&sVp[(b * 8 + u) * VPS + pc];
            float p0 = sP[((b * 4 + h) * 8 + s0) * 9 + u];
            float p1 = sP[((b * 4 + h) * 8 + s1) * 9 + u];
            o0[0] += p0 * v4.x; o0[1] += p0 * v4.y; o0[2] += p0 * v4.z; o0[3] += p0 * v4.w;
            o1[0] += p1 * v4.x; o1[1] += p1 * v4.y; o1[2] += p1 * v4.z; o1[3] += p1 * v4.w;
        }
        *(float4*)&sO[(b * 8 + s0) * OPS + c0] = make_float4(o0[0], o0[1], o0[2], o0[3]);
        *(float4*)&sO[(b * 8 + s1) * OPS + c0] = make_float4(o1[0], o1[1], o1[2], o1[3]);
    }
    __syncthreads();

    // ---- fc + residual ; stage W2 + h into dead Q/K/V space ----
    {
        int r0 = w * 2, r1 = r0 + 1;
        int c0 = lane * 2;
        u64 p0 = 0ull, p1 = 0ull;
        const float* o0 = sO + r0 * OPS;
        const float* o1 = sO + r1 * OPS;
#pragma unroll 4
        for (int k = 0; k < 128; k++) {
            u64 w2 = *(const u64*)&wfc[k * 64 + c0];
            fma2(p0, bc2(o0[k]), w2);
            fma2(p1, bc2(o1[k]), w2);
        }
        float2 f0 = up2(p0), f1 = up2(p1);
        sF[r0 * FPS + c0]     = f0.x + sA[r0 * 64 + c0];
        sF[r0 * FPS + c0 + 1] = f0.y + sA[r0 * 64 + c0 + 1];
        sF[r1 * FPS + c0]     = f1.x + sA[r1 * 64 + c0];
        sF[r1 * FPS + c0 + 1] = f1.y + sA[r1 * 64 + c0 + 1];
        // stage W2 (8064 floats) and the 4 h rows (256 floats)
        for (int idx = tid; idx < 8064; idx += 512) sW2[idx] = W2[idx];
        if (tid < 256) sH[tid] = hsrc[(size_t)blockIdx.x * 4 * 64 + tid];
    }
    __syncthreads();

    // ---- LayerNorm stats ----
    if (tid < 32) {
        const float* fr = sF + tid * FPS;
        float m = 0.f;
#pragma unroll
        for (int c = 0; c < 64; c++) m += fr[c];
        m *= (1.f / 64.f);
        float v = 0.f;
#pragma unroll
        for (int c = 0; c < 64; c++) { float d = fr[c] - m; v += d * d; }
        v *= (1.f / 64.f);
        sMu[tid] = m;
        sRs[tid] = rsqrtf(v + 1e-6f);
    }
    __syncthreads();

    // ---- normalize sF in place ----
    for (int idx = tid; idx < 2048; idx += 512) {
        int r = idx >> 6, c = idx & 63;
        sF[r * FPS + c] = (sF[r * FPS + c] - sMu[r]) * sRs[r] * gln[c] + bln[c];
    }
    __syncthreads();

    // ---- mlp2: warps 0..3, one output row each ----
    if (w < 4) {
        size_t R = (size_t)blockIdx.x * 4 + w;
        float acc[14];
#pragma unroll
        for (int c = 0; c < 14; c++) acc[c] = 0.f;
        for (int k = lane; k < 576; k += 32) {
            float v;
            if (k < 64) v = sH[w * 64 + k];
            else {
                int kk = k - 64;
                v = sF[(w * 8 + (kk >> 6)) * FPS + (kk & 63)];
            }
            const float* wrow = sW2 + k * 14;
#pragma unroll
            for (int c = 0; c < 14; c++) acc[c] += v * wrow[c];
        }
#pragma unroll
        for (int c = 0; c < 14; c++) {
            float a = acc[c];
            for (int o = 16; o > 0; o >>= 1) a += __shfl_down_sync(0xffffffffu, a, o);
            if (lane == 0) qout[R * 14 + c] = a + b2[c];
        }
    }
}

// ---------------- launch ----------------
extern "C" void kernel_launch(void* const* d_in, const int* in_sizes, int n_in,
                              void* d_out, int out_size)
{
    const float* inputs = (const float*)d_in[0];
    const float* hidden = (const float*)d_in[1];
    const float* noise  = (const float*)d_in[2];
    const float* w_mlp1 = (const float*)d_in[3];
    const float* b_mlp1 = (const float*)d_in[4];
    const float* w_ih   = (const float*)d_in[5];
    const float* b_ih   = (const float*)d_in[6];
    const float* w_hh   = (const float*)d_in[7];
    const float* b_hh   = (const float*)d_in[8];
    const float* w_ae1  = (const float*)d_in[9];
    const float* b_ae1  = (const float*)d_in[10];
    const float* g_ae   = (const float*)d_in[11];
    const float* be_ae  = (const float*)d_in[12];
    const float* w_ae2  = (const float*)d_in[13];
    const float* b_ae2  = (const float*)d_in[14];
    const float* w_in1  = (const float*)d_in[15];
    const float* b_in1  = (const float*)d_in[16];
    const float* g_in   = (const float*)d_in[17];
    const float* be_in  = (const float*)d_in[18];
    const float* w_in2  = (const float*)d_in[19];
    const float* b_in2  = (const float*)d_in[20];
    const float* w_q    = (const float*)d_in[21];
    const float* w_k    = (const float*)d_in[22];
    const float* w_v    = (const float*)d_in[23];
    const float* w_fc   = (const float*)d_in[24];
    const float* g_ln   = (const float*)d_in[25];
    const float* b_ln   = (const float*)d_in[26];
    const float* w_mlp2 = (const float*)d_in[27];
    const float* b_mlp2 = (const float*)d_in[28];

    float* out = (float*)d_out;
    float* q_out   = out;
    float* h_out   = out + NROWS * NACT;
    float* kld_out = h_out + NROWS * Hdim;

    static int attn_smem_set = 0;
    const int ATTN_SMEM = ATTN_SMEM_FLOATS * 4;
    if (!attn_smem_set) {
        cudaFuncSetAttribute(k_attn, cudaFuncAttributeMaxDynamicSharedMemorySize, ATTN_SMEM);
        attn_smem_set = 1;
    }

    // launch index 3 (k_ae2) is the ncu capture slot
    k_zero<<<1, 640>>>();
    k_mlp1_gru<<<NROWS / 32, 512>>>(inputs, hidden, w_mlp1, b_mlp1, w_ih, b_ih, w_hh, b_hh, h_out);
    k_ae1<<<NROWS / 32, 256>>>(h_out, w_ae1, b_ae1);
    k_ae2<<<dim3(NROWS / 32, 4), 256>>>(w_ae2, b_ae2, noise, g_ae, be_ae);
    k_LR<<<NROWS / 32, 256>>>(h_out, w_in1);
    k_cross<<<BSZ / 32, 256>>>();
    k_infer<<<BSZ, 256>>>(w_in2, b_in2, b_in1, g_in, be_in, kld_out);
    k_pack<<<(64 * 384 + 255) / 256, 256>>>(w_q, w_k, w_v);
    k_attn<<<NROWS / 4, 512, ATTN_SMEM>>>(h_out, w_fc, g_ln, b_ln, w_mlp2, b_mlp2, q_out);
}

// round 12
// speedup vs baseline: 1.1089x; 1.1089x over previous
#include <cuda_runtime.h>
#include <math.h>

#define NAg 8
#define Hdim 64
#define LATENT 512
#define NACT 14
#define BSZ 4096
#define NROWS 32768   // BSZ*NAg
#define LN0002 (-6.2146080984221914f)

typedef unsigned long long u64;

// ---- packed fp32x2 helpers ----
__device__ __forceinline__ u64 bc2(float x) {
    u64 r; asm("mov.b64 %0, {%1, %2};" : "=l"(r) : "f"(x), "f"(x)); return r;
}
__device__ __forceinline__ void fma2(u64& d, u64 a, u64 b) {
    asm("fma.rn.f32x2 %0, %1, %2, %3;" : "=l"(d) : "l"(a), "l"(b), "l"(d));
}
__device__ __forceinline__ float2 up2(u64 v) {
    float lo, hi; asm("mov.b64 {%0, %1}, %2;" : "=f"(lo), "=f"(hi) : "l"(v));
    return make_float2(lo, hi);
}
__device__ __forceinline__ u64 lds2(const float* p) { return *(const u64*)p; }
__device__ __forceinline__ float tanh_fast(float x) {
    float r; asm("tanh.approx.f32 %0, %1;" : "=f"(r) : "f"(x)); return r;
}
__device__ __forceinline__ float sigmoid_fast(float x) {
    return 1.f / (1.f + __expf(-x));
}

// ---------------- scratch ----------------
__device__ float g_uae[NROWS * 128];
__device__ float g_ae_acc[2 * 128];
__device__ float g_mean[NROWS * 512];
__device__ float g_lvar[NROWS * 512];
__device__ float g_aw[NROWS * 512];
__device__ float g_L[NROWS * 128];
__device__ float g_R[NROWS * 128];
__device__ float g_in_acc[5 * 128];
__device__ float g_wqkv[64 * 384];
__device__ float g_att[NROWS * 512];

__global__ void k_zero() {
    int i = threadIdx.x;
    if (i < 256) g_ae_acc[i] = 0.f;
    if (i < 640) g_in_acc[i] = 0.f;
}

// ---------------- kernel A: fused mlp1 + GRU (512 thr, fast activations) ----------------
__global__ __launch_bounds__(512) void k_mlp1_gru(
    const float* __restrict__ in, const float* __restrict__ hin,
    const float* __restrict__ W1, const float* __restrict__ b1,
    const float* __restrict__ Wih, const float* __restrict__ bih,
    const float* __restrict__ Whh, const float* __restrict__ bhh,
    float* __restrict__ hout)
{
    __shared__ float sInT[96][34];
    __shared__ float sXT[64][34];
    __shared__ float sHT[64][34];
    int tid = threadIdx.x;
    int row0 = blockIdx.x * 32;

    for (int idx = tid; idx < 32 * 96; idx += 512) {
        int r = idx / 96, k = idx % 96;
        sInT[k][r] = in[(row0 + r) * 96 + k];
    }
    for (int idx = tid; idx < 32 * 64; idx += 512) {
        int r = idx / 64, k = idx % 64;
        sHT[k][r] = hin[(row0 + r) * 64 + k];
    }
    __syncthreads();

    int c = tid & 63;
    int rg = tid >> 6;      // 0..7 -> rows rg*4..+3
    {
        u64 acc2[2] = {0ull, 0ull};
        for (int k = 0; k < 96; k++) {
            u64 w2 = bc2(W1[k * 64 + c]);
#pragma unroll
            for (int t = 0; t < 2; t++)
                fma2(acc2[t], lds2(&sInT[k][rg * 4 + 2 * t]), w2);
        }
        float b = b1[c];
#pragma unroll
        for (int t = 0; t < 2; t++) {
            float2 v = up2(acc2[t]);
            v.x += b; v.y += b;
            v.x = v.x > 0.f ? v.x : 0.f;
            v.y = v.y > 0.f ? v.y : 0.f;
            *(float2*)&sXT[c][rg * 4 + 2 * t] = v;
        }
    }
    __syncthreads();

    {
        int j = c;
        u64 axr2[2], axz2[2], axn2[2], ahr2[2], ahz2[2], ahn2[2];
#pragma unroll
        for (int t = 0; t < 2; t++) { axr2[t]=axz2[t]=axn2[t]=ahr2[t]=ahz2[t]=ahn2[t]=0ull; }
        for (int k = 0; k < 64; k++) {
            u64 wr = bc2(Wih[k * 192 + j]);
            u64 wz = bc2(Wih[k * 192 + 64 + j]);
            u64 wn = bc2(Wih[k * 192 + 128 + j]);
            u64 vr = bc2(Whh[k * 192 + j]);
            u64 vz = bc2(Whh[k * 192 + 64 + j]);
            u64 vn = bc2(Whh[k * 192 + 128 + j]);
#pragma unroll
            for (int t = 0; t < 2; t++) {
                u64 x2 = lds2(&sXT[k][rg * 4 + 2 * t]);
                u64 h2 = lds2(&sHT[k][rg * 4 + 2 * t]);
                fma2(axr2[t], x2, wr); fma2(axz2[t], x2, wz); fma2(axn2[t], x2, wn);
                fma2(ahr2[t], h2, vr); fma2(ahz2[t], h2, vz); fma2(ahn2[t], h2, vn);
            }
        }
        float br = bih[j], bz = bih[64 + j], bn_ = bih[128 + j];
        float cr = bhh[j], cz = bhh[64 + j], cn = bhh[128 + j];
#pragma unroll
        for (int t = 0; t < 2; t++) {
            float2 xr = up2(axr2[t]), xz = up2(axz2[t]), xn = up2(axn2[t]);
            float2 hr = up2(ahr2[t]), hz = up2(ahz2[t]), hn = up2(ahn2[t]);
#pragma unroll
            for (int lz = 0; lz < 2; lz++) {
                int r = rg * 4 + 2 * t + lz;
                float XR = lz ? xr.y : xr.x, XZ = lz ? xz.y : xz.x, XN = lz ? xn.y : xn.x;
                float HR = lz ? hr.y : hr.x, HZ = lz ? hz.y : hz.x, HN = lz ? hn.y : hn.x;
                float rg_ = sigmoid_fast((XR + br) + (HR + cr));
                float zg  = sigmoid_fast((XZ + bz) + (HZ + cz));
                float ng  = tanh_fast((XN + bn_) + rg_ * (HN + cn));
                float hprev = sHT[j][r];
                hout[(row0 + r) * 64 + j] = (1.f - zg) * ng + zg * hprev;
            }
        }
    }
}

// ---------------- kernel B: ae1 GEMM + column stats ----------------
__global__ void k_ae1(const float* __restrict__ hsrc,
                      const float* __restrict__ Wae1, const float* __restrict__ bae1)
{
    __shared__ float sHT[64][34];
    __shared__ float sred[256];
    int tid = threadIdx.x;
    int row0 = blockIdx.x * 32;
    for (int idx = tid; idx < 32 * 64; idx += 256) {
        int r = idx / 64, k = idx % 64;
        sHT[k][r] = hsrc[(row0 + r) * 64 + k];
    }
    __syncthreads();
    int c = tid & 127;
    int rg = tid >> 7;
    u64 acc2[8];
#pragma unroll
    for (int t = 0; t < 8; t++) acc2[t] = 0ull;
    for (int k = 0; k < 64; k++) {
        u64 w2 = bc2(Wae1[k * 128 + c]);
#pragma unroll
        for (int t = 0; t < 8; t++)
            fma2(acc2[t], lds2(&sHT[k][rg * 16 + 2 * t]), w2);
    }
    float b = bae1[c];
    float s = 0.f, q = 0.f;
#pragma unroll
    for (int t = 0; t < 8; t++) {
        float2 u2 = up2(acc2[t]);
        float u0 = u2.x + b, u1 = u2.y + b;
        g_uae[(row0 + rg * 16 + 2 * t) * 128 + c] = u0;
        g_uae[(row0 + rg * 16 + 2 * t + 1) * 128 + c] = u1;
        s += u0 + u1; q += u0 * u0 + u1 * u1;
    }
    sred[tid] = s; __syncthreads();
    if (tid < 128) atomicAdd(&g_ae_acc[tid], sred[tid] + sred[tid + 128]);
    __syncthreads();
    sred[tid] = q; __syncthreads();
    if (tid < 128) atomicAdd(&g_ae_acc[128 + tid], sred[tid] + sred[tid + 128]);
}

// ---------------- kernel D: ae2 GEMM (column-paired f32x2, float4 row loads) ----------------
__global__ __launch_bounds__(256) void k_ae2(
    const float* __restrict__ Wae2, const float* __restrict__ bae2,
    const float* __restrict__ noise,
    const float* __restrict__ gae, const float* __restrict__ beae)
{
    __shared__ __align__(16) float sUT[128 * 36];   // [k][row], stride 36 (16B aligned rows)
    __shared__ float s_sc[128], s_sh[128];
    int tid = threadIdx.x;
    int row0 = blockIdx.x * 32;
    int p = blockIdx.y;

    if (tid < 128) {
        float m = g_ae_acc[tid] * (1.f / 32768.f);
        float var = g_ae_acc[128 + tid] * (1.f / 32768.f) - m * m;
        float s = rsqrtf(var + 1e-5f) * gae[tid];
        s_sc[tid] = s;
        s_sh[tid] = beae[tid] - m * s;
    }
    __syncthreads();

    for (int idx = tid; idx < 32 * 128; idx += 256) {
        int r = idx >> 7, k = idx & 127;
        float u = g_uae[(size_t)row0 * 128 + idx];
        float v = u * s_sc[k] + s_sh[k];
        sUT[k * 36 + r] = v >= 0.f ? v : 0.01f * v;
    }
    __syncthreads();

    int rg = tid >> 5;        // 0..7 -> rows rg*4..+3
    int cg = tid & 31;
    int cm = p * 128 + cg * 4;
    int cv = 512 + cm;
    // acc[row][pair]: pairs 0,1 = mean cols cm..cm+3 ; 2,3 = var cols
    u64 acc[4][4];
#pragma unroll
    for (int i = 0; i < 4; i++)
#pragma unroll
        for (int j = 0; j < 4; j++) acc[i][j] = 0ull;

    for (int k = 0; k < 128; k++) {
        float4 a4 = *(const float4*)&sUT[k * 36 + rg * 4];
        ulonglong2 wm = *(const ulonglong2*)&Wae2[k * 1024 + cm];
        ulonglong2 wv = *(const ulonglong2*)&Wae2[k * 1024 + cv];
        u64 b0 = bc2(a4.x), b1 = bc2(a4.y), b2 = bc2(a4.z), b3 = bc2(a4.w);
        fma2(acc[0][0], b0, wm.x); fma2(acc[0][1], b0, wm.y);
        fma2(acc[0][2], b0, wv.x); fma2(acc[0][3], b0, wv.y);
        fma2(acc[1][0], b1, wm.x); fma2(acc[1][1], b1, wm.y);
        fma2(acc[1][2], b1, wv.x); fma2(acc[1][3], b1, wv.y);
        fma2(acc[2][0], b2, wm.x); fma2(acc[2][1], b2, wm.y);
        fma2(acc[2][2], b2, wv.x); fma2(acc[2][3], b2, wv.y);
        fma2(acc[3][0], b3, wm.x); fma2(acc[3][1], b3, wm.y);
        fma2(acc[3][2], b3, wv.x); fma2(acc[3][3], b3, wv.y);
    }
    float4 bm = *(const float4*)&bae2[cm];
    float4 bv = *(const float4*)&bae2[cv];
#pragma unroll
    for (int i = 0; i < 4; i++) {
        size_t row = row0 + rg * 4 + i;
        float2 m01 = up2(acc[i][0]), m23 = up2(acc[i][1]);
        float2 l01 = up2(acc[i][2]), l23 = up2(acc[i][3]);
        float m0 = m01.x + bm.x, m1 = m01.y + bm.y;
        float m2 = m23.x + bm.z, m3 = m23.y + bm.w;
        float l0 = fmaxf(l01.x + bv.x, LN0002);
        float l1 = fmaxf(l01.y + bv.y, LN0002);
        float l2 = fmaxf(l23.x + bv.z, LN0002);
        float l3 = fmaxf(l23.y + bv.w, LN0002);
        size_t off = row * 512 + cm;
        float4 nz = *(const float4*)&noise[off];
        *(float4*)&g_mean[off] = make_float4(m0, m1, m2, m3);
        *(float4*)&g_lvar[off] = make_float4(l0, l1, l2, l3);
        *(float4*)&g_aw[off]   = make_float4(m0 + __expf(0.5f * l0) * nz.x,
                                             m1 + __expf(0.5f * l1) * nz.y,
                                             m2 + __expf(0.5f * l2) * nz.z,
                                             m3 + __expf(0.5f * l3) * nz.w);
    }
}

// ---------------- kernel F: L/R GEMMs + column stats ----------------
__global__ void k_LR(const float* __restrict__ hsrc, const float* __restrict__ Win1)
{
    __shared__ float sHT[64][34];
    int tid = threadIdx.x;
    int row0 = blockIdx.x * 32;
    for (int idx = tid; idx < 32 * 64; idx += 256) {
        int r = idx / 64, k = idx % 64;
        sHT[k][r] = hsrc[(row0 + r) * 64 + k];
    }
    __syncthreads();
    int cc = tid;
    int cm = cc & 127;
    u64 acc2[16];
#pragma unroll
    for (int t = 0; t < 16; t++) acc2[t] = 0ull;
    for (int k = 0; k < 64; k++) {
        float w = (cc < 128) ? Win1[k * 128 + cm] : Win1[(64 + k) * 128 + cm];
        u64 w2 = bc2(w);
#pragma unroll
        for (int t = 0; t < 16; t++)
            fma2(acc2[t], lds2(&sHT[k][2 * t]), w2);
    }
    float* dst = (cc < 128) ? g_L : g_R;
    float s = 0.f, q = 0.f;
#pragma unroll
    for (int t = 0; t < 16; t++) {
        float2 v2 = up2(acc2[t]);
        dst[(row0 + 2 * t) * 128 + cm] = v2.x;
        dst[(row0 + 2 * t + 1) * 128 + cm] = v2.y;
        s += v2.x + v2.y; q += v2.x * v2.x + v2.y * v2.y;
    }
    atomicAdd(&g_in_acc[cc], s);
    atomicAdd(&g_in_acc[256 + cc], q);
}

__global__ void k_cross() {
    __shared__ float sred[256];
    int tid = threadIdx.x;
    int c = tid & 127;
    int bg = tid >> 7;
    int b0 = blockIdx.x * 32;
    float cr = 0.f;
    for (int bb = bg * 16; bb < bg * 16 + 16; bb++) {
        int b = b0 + bb;
        float sl = 0.f, sr = 0.f;
#pragma unroll
        for (int i = 0; i < 8; i++) {
            sl += g_L[(b * 8 + i) * 128 + c];
            sr += g_R[(b * 8 + i) * 128 + c];
        }
        cr += sl * sr;
    }
    sred[tid] = cr; __syncthreads();
    if (tid < 128) atomicAdd(&g_in_acc[512 + tid], sred[tid] + sred[tid + 128]);
}

// ---------------- kernel I: infer GEMM + KLD (transposed sUT, float4 loads) ----------------
__global__ __launch_bounds__(256) void k_infer(
    const float* __restrict__ Win2, const float* __restrict__ bin2,
    const float* __restrict__ bin1,
    const float* __restrict__ gin, const float* __restrict__ bein,
    float* __restrict__ kld_out)
{
    __shared__ float sL[8 * 128], sR[8 * 128];
    __shared__ __align__(16) float sUT[128 * 36];   // [k][row 0..31]
    __shared__ float sIP[32 * 128];
    __shared__ float s_sc[128], s_sh[128];
    __shared__ float sred[256];
    int b = blockIdx.x;
    int tid = threadIdx.x;
    for (int idx = tid; idx < 1024; idx += 256) {
        sL[idx] = g_L[(size_t)b * 1024 + idx];
        sR[idx] = g_R[(size_t)b * 1024 + idx];
    }
    if (tid < 128) {
        int c = tid;
        float sl = g_in_acc[c], sr = g_in_acc[128 + c];
        float ql = g_in_acc[256 + c], qr = g_in_acc[384 + c];
        float cr = g_in_acc[512 + c];
        float beta = bin1[c];
        const float Nr = 262144.f;
        float mean = 8.f * (sl + sr) / Nr + beta;
        float e2 = (8.f * ql + 8.f * qr + 2.f * cr + 16.f * beta * (sl + sr)) / Nr + beta * beta;
        float var = e2 - mean * mean;
        float s = rsqrtf(var + 1e-5f) * gin[c];
        s_sc[c] = s;
        s_sh[c] = bein[c] + (beta - mean) * s;
    }
    __syncthreads();

    int wr = tid >> 5;   // 0..7 -> rows wr*4..+3
    int cg = tid & 31;
    float4 bia = *(const float4*)&bin2[cg * 4];
    float kacc = 0.f;

    for (int half = 0; half < 2; half++) {
        int i0 = half * 4;
        for (int idx = tid; idx < 4096; idx += 256) {
            int r = idx >> 7, k = idx & 127;
            int ii = r >> 3, j = r & 7;
            float v = (sL[(i0 + ii) * 128 + k] + sR[j * 128 + k]) * s_sc[k] + s_sh[k];
            sUT[k * 36 + r] = v >= 0.f ? v : 0.01f * v;
        }
        __syncthreads();
        u64 acc2[4][2];
#pragma unroll
        for (int i = 0; i < 4; i++) { acc2[i][0] = 0ull; acc2[i][1] = 0ull; }
        for (int k = 0; k < 128; k++) {
            float4 a4 = *(const float4*)&sUT[k * 36 + wr * 4];
            ulonglong2 w = *(const ulonglong2*)&Win2[k * 128 + cg * 4];
            u64 b0 = bc2(a4.x), b1 = bc2(a4.y), b2 = bc2(a4.z), b3 = bc2(a4.w);
            fma2(acc2[0][0], b0, w.x); fma2(acc2[0][1], b0, w.y);
            fma2(acc2[1][0], b1, w.x); fma2(acc2[1][1], b1, w.y);
            fma2(acc2[2][0], b2, w.x); fma2(acc2[2][1], b2, w.y);
            fma2(acc2[3][0], b3, w.x); fma2(acc2[3][1], b3, w.y);
        }
#pragma unroll
        for (int i = 0; i < 4; i++) {
            float2 a01 = up2(acc2[i][0]), a23 = up2(acc2[i][1]);
            *(float4*)&sIP[(wr * 4 + i) * 128 + cg * 4] =
                make_float4(a01.x + bia.x, a01.y + bia.y, a23.x + bia.z, a23.y + bia.w);
        }
        __syncthreads();
        for (int ii = 0; ii < 4; ii++) {
            const float* mrow = g_mean + (size_t)(b * 8 + i0 + ii) * 512;
            const float* vrow = g_lvar + (size_t)(b * 8 + i0 + ii) * 512;
            for (int idx = tid; idx < 512; idx += 256) {
                int j = idx >> 6, d = idx & 63;
                float im  = sIP[(ii * 8 + j) * 128 + d];
                float liv = fmaxf(sIP[(ii * 8 + j) * 128 + 64 + d], LN0002);
                float riv = __expf(-liv);
                float lv  = vrow[idx];
                float v0  = __expf(lv);
                float dm  = mrow[idx] - im;
                kacc += 0.5f * (liv - lv) + 0.5f * (v0 + dm * dm) * riv - 0.5f;
            }
        }
        __syncthreads();
    }
    sred[tid] = kacc; __syncthreads();
    for (int s = 128; s > 0; s >>= 1) {
        if (tid < s) sred[tid] += sred[tid + s];
        __syncthreads();
    }
    if (tid == 0) kld_out[b] = sred[0] * (1.f / 4096.f);
}

__global__ void k_pack(const float* __restrict__ wq, const float* __restrict__ wk,
                       const float* __restrict__ wv)
{
    int idx = blockIdx.x * 256 + threadIdx.x;
    if (idx >= 64 * 384) return;
    int k = idx / 384, c = idx % 384;
    float v = (c < 128) ? wq[k * 128 + c] : (c < 256) ? wk[k * 128 + c - 128] : wv[k * 128 + c - 256];
    g_wqkv[idx] = v;
}

// ---------------- kernel K: fused MHA + layernorm -> g_att ----------------
#define QPS 133
#define VPS 144
#define OPS 132
#define FPS 67
#define OFF_A   0
#define OFF_Q   2048
#define OFF_K   6304
#define OFF_V   10560
#define OFF_P   15168
#define OFF_O   16320
#define OFF_F   20544
#define OFF_MU  22688
#define OFF_RS  22720
#define ATTN_SMEM_FLOATS 22752

__global__ __launch_bounds__(512) void k_attn(
    const float* __restrict__ wfc,
    const float* __restrict__ gln, const float* __restrict__ bln)
{
    extern __shared__ float sm[];
    float* sA  = sm + OFF_A;
    float* sQp = sm + OFF_Q;
    float* sKp = sm + OFF_K;
    float* sVp = sm + OFF_V;
    float* sP  = sm + OFF_P;
    float* sO  = sm + OFF_O;
    float* sF  = sm + OFF_F;
    float* sMu = sm + OFF_MU;
    float* sRs = sm + OFF_RS;

    int tid = threadIdx.x;
    int w = tid >> 5;
    int lane = tid & 31;

    size_t base = (size_t)blockIdx.x * 2048;
    for (int idx = tid; idx < 2048; idx += 512) sA[idx] = g_aw[base + idx];
    __syncthreads();

    {
        int r0 = w * 2, r1 = r0 + 1;
        int cl = lane * 4;
        int h = cl >> 5, within = cl & 31;
        const float* ar0 = sA + r0 * 64;
        const float* ar1 = sA + r1 * 64;
#pragma unroll
        for (int pass = 0; pass < 3; pass++) {
            u64 a0p[2] = {0ull, 0ull}, a1p[2] = {0ull, 0ull};
            const float* wp = g_wqkv + pass * 128 + cl;
#pragma unroll 4
            for (int k = 0; k < 64; k++) {
                ulonglong2 w4 = *(const ulonglong2*)&wp[k * 384];
                u64 a0 = bc2(ar0[k]), a1 = bc2(ar1[k]);
                fma2(a0p[0], a0, w4.x); fma2(a0p[1], a0, w4.y);
                fma2(a1p[0], a1, w4.x); fma2(a1p[1], a1, w4.y);
            }
            float2 q001 = up2(a0p[0]), q023 = up2(a0p[1]);
            float2 q101 = up2(a1p[0]), q123 = up2(a1p[1]);
            if (pass < 2) {
                float* dst = (pass == 0) ? sQp : sKp;
                int pc = h * 33 + within;
                dst[r0 * QPS + pc]     = q001.x; dst[r0 * QPS + pc + 1] = q001.y;
                dst[r0 * QPS + pc + 2] = q023.x; dst[r0 * QPS + pc + 3] = q023.y;
                dst[r1 * QPS + pc]     = q101.x; dst[r1 * QPS + pc + 1] = q101.y;
                dst[r1 * QPS + pc + 2] = q123.x; dst[r1 * QPS + pc + 3] = q123.y;
            } else {
                int pc = h * 36 + within;
                *(float4*)&sVp[r0 * VPS + pc] = make_float4(q001.x, q001.y, q023.x, q023.y);
                *(float4*)&sVp[r1 * VPS + pc] = make_float4(q101.x, q101.y, q123.x, q123.y);
            }
        }
    }
    __syncthreads();

    {
        int b = w >> 2, h = w & 3;
        int s = lane & 7, dgrp = lane >> 3;
        const float* qb = sQp + (b * 8 + s) * QPS + h * 33 + dgrp * 8;
        float q[8];
#pragma unroll
        for (int d = 0; d < 8; d++) q[d] = qb[d];
        float scv[8];
#pragma unroll
        for (int u = 0; u < 8; u++) {
            const float* kr = sKp + (b * 8 + u) * QPS + h * 33 + dgrp * 8;
            float p = 0.f;
#pragma unroll
            for (int d = 0; d < 8; d++) p += q[d] * kr[d];
            scv[u] = p;
        }
#pragma unroll
        for (int u = 0; u < 8; u++) {
            scv[u] += __shfl_xor_sync(0xffffffffu, scv[u], 8);
            scv[u] += __shfl_xor_sync(0xffffffffu, scv[u], 16);
        }
        if (lane < 8) {
            float mx = -1e30f;
#pragma unroll
            for (int u = 0; u < 8; u++) {
                scv[u] *= 0.17677669529663687f;
                mx = fmaxf(mx, scv[u]);
            }
            float sum = 0.f;
#pragma unroll
            for (int u = 0; u < 8; u++) { scv[u] = __expf(scv[u] - mx); sum += scv[u]; }
            float inv = 1.f / sum;
            float* pr = sP + ((b * 4 + h) * 8 + s) * 9;
#pragma unroll
            for (int u = 0; u < 8; u++) pr[u] = scv[u] * inv;
        }
    }
    __syncthreads();

    {
        int b = w >> 2;
        int s0 = (w & 3) * 2, s1 = s0 + 1;
        int c0 = lane * 4;
        int h = c0 >> 5;
        int pc = h * 36 + (c0 & 31);
        float o0[4], o1[4];
#pragma unroll
        for (int t = 0; t < 4; t++) { o0[t] = 0.f; o1[t] = 0.f; }
#pragma unroll
        for (int u = 0; u < 8; u++) {
            float4 v4 = *(const float4*)&sVp[(b * 8 + u) * VPS + pc];
            float p0 = sP[((b * 4 + h) * 8 + s0) * 9 + u];
            float p1 = sP[((b * 4 + h) * 8 + s1) * 9 + u];
            o0[0] += p0 * v4.x; o0[1] += p0 * v4.y; o0[2] += p0 * v4.z; o0[3] += p0 * v4.w;
            o1[0] += p1 * v4.x; o1[1] += p1 * v4.y; o1[2] += p1 * v4.z; o1[3] += p1 * v4.w;
        }
        *(float4*)&sO[(b * 8 + s0) * OPS + c0] = make_float4(o0[0], o0[1], o0[2], o0[3]);
        *(float4*)&sO[(b * 8 + s1) * OPS + c0] = make_float4(o1[0], o1[1], o1[2], o1[3]);
    }
    __syncthreads();

    {
        int r0 = w * 2, r1 = r0 + 1;
        int c0 = lane * 2;
        u64 p0 = 0ull, p1 = 0ull;
        const float* o0 = sO + r0 * OPS;
        const float* o1 = sO + r1 * OPS;
#pragma unroll 4
        for (int k = 0; k < 128; k++) {
            u64 w2 = *(const u64*)&wfc[k * 64 + c0];
            fma2(p0, bc2(o0[k]), w2);
            fma2(p1, bc2(o1[k]), w2);
        }
        float2 f0 = up2(p0), f1 = up2(p1);
        sF[r0 * FPS + c0]     = f0.x + sA[r0 * 64 + c0];
        sF[r0 * FPS + c0 + 1] = f0.y + sA[r0 * 64 + c0 + 1];
        sF[r1 * FPS + c0]     = f1.x + sA[r1 * 64 + c0];
        sF[r1 * FPS + c0 + 1] = f1.y + sA[r1 * 64 + c0 + 1];
    }
    __syncthreads();

    if (tid < 32) {
        const float* fr = sF + tid * FPS;
        float m = 0.f;
#pragma unroll
        for (int c = 0; c < 64; c++) m += fr[c];
        m *= (1.f / 64.f);
        float v = 0.f;
#pragma unroll
        for (int c = 0; c < 64; c++) { float d = fr[c] - m; v += d * d; }
        v *= (1.f / 64.f);
        sMu[tid] = m;
        sRs[tid] = rsqrtf(v + 1e-6f);
    }
    __syncthreads();

    for (int idx = tid; idx < 2048; idx += 512) {
        int r = idx >> 6, c = idx & 63;
        g_att[base + idx] = (sF[r * FPS + c] - sMu[r]) * sRs[r] * gln[c] + bln[c];
    }
}

// ---------------- kernel L: mlp2 ----------------
__global__ void k_mlp2(const float* __restrict__ hsrc,
                       const float* __restrict__ W2, const float* __restrict__ b2,
                       float* __restrict__ qout)
{
    __shared__ float sWt[14 * 576];
    int tid = threadIdx.x;
    for (int idx = tid; idx < 14 * 576; idx += 256) {
        int c = idx / 576, k = idx % 576;
        sWt[c * 576 + k] = W2[k * 14 + c];
    }
    __syncthreads();
    int w = tid >> 5, l = tid & 31;
    size_t row = (size_t)blockIdx.x * 8 + w;
    const float* hr = hsrc + row * 64;
    const float* ar = g_att + row * 512;
    float acc[14];
#pragma unroll
    for (int c = 0; c < 14; c++) acc[c] = 0.f;
    for (int k = l; k < 576; k += 32) {
        float v = (k < 64) ? hr[k] : ar[k - 64];
#pragma unroll
        for (int c = 0; c < 14; c++) acc[c] += v * sWt[c * 576 + k];
    }
#pragma unroll
    for (int c = 0; c < 14; c++) {
        float a = acc[c];
        for (int o = 16; o > 0; o >>= 1) a += __shfl_down_sync(0xffffffffu, a, o);
        if (l == 0) qout[row * 14 + c] = a + b2[c];
    }
}

// ---------------- launch ----------------
extern "C" void kernel_launch(void* const* d_in, const int* in_sizes, int n_in,
                              void* d_out, int out_size)
{
    const float* inputs = (const float*)d_in[0];
    const float* hidden = (const float*)d_in[1];
    const float* noise  = (const float*)d_in[2];
    const float* w_mlp1 = (const float*)d_in[3];
    const float* b_mlp1 = (const float*)d_in[4];
    const float* w_ih   = (const float*)d_in[5];
    const float* b_ih   = (const float*)d_in[6];
    const float* w_hh   = (const float*)d_in[7];
    const float* b_hh   = (const float*)d_in[8];
    const float* w_ae1  = (const float*)d_in[9];
    const float* b_ae1  = (const float*)d_in[10];
    const float* g_ae   = (const float*)d_in[11];
    const float* be_ae  = (const float*)d_in[12];
    const float* w_ae2  = (const float*)d_in[13];
    const float* b_ae2  = (const float*)d_in[14];
    const float* w_in1  = (const float*)d_in[15];
    const float* b_in1  = (const float*)d_in[16];
    const float* g_in   = (const float*)d_in[17];
    const float* be_in  = (const float*)d_in[18];
    const float* w_in2  = (const float*)d_in[19];
    const float* b_in2  = (const float*)d_in[20];
    const float* w_q    = (const float*)d_in[21];
    const float* w_k    = (const float*)d_in[22];
    const float* w_v    = (const float*)d_in[23];
    const float* w_fc   = (const float*)d_in[24];
    const float* g_ln   = (const float*)d_in[25];
    const float* b_ln   = (const float*)d_in[26];
    const float* w_mlp2 = (const float*)d_in[27];
    const float* b_mlp2 = (const float*)d_in[28];

    float* out = (float*)d_out;
    float* q_out   = out;
    float* h_out   = out + NROWS * NACT;
    float* kld_out = h_out + NROWS * Hdim;

    static int attn_smem_set = 0;
    const int ATTN_SMEM = ATTN_SMEM_FLOATS * 4;
    if (!attn_smem_set) {
        cudaFuncSetAttribute(k_attn, cudaFuncAttributeMaxDynamicSharedMemorySize, ATTN_SMEM);
        attn_smem_set = 1;
    }

    // launch index 3 (k_ae2) is the ncu capture slot
    k_zero<<<1, 640>>>();
    k_mlp1_gru<<<NROWS / 32, 512>>>(inputs, hidden, w_mlp1, b_mlp1, w_ih, b_ih, w_hh, b_hh, h_out);
    k_ae1<<<NROWS / 32, 256>>>(h_out, w_ae1, b_ae1);
    k_ae2<<<dim3(NROWS / 32, 4), 256>>>(w_ae2, b_ae2, noise, g_ae, be_ae);
    k_LR<<<NROWS / 32, 256>>>(h_out, w_in1);
    k_cross<<<BSZ / 32, 256>>>();
    k_infer<<<BSZ, 256>>>(w_in2, b_in2, b_in1, g_in, be_in, kld_out);
    k_pack<<<(64 * 384 + 255) / 256, 256>>>(w_q, w_k, w_v);
    k_attn<<<NROWS / 4, 512, ATTN_SMEM>>>(w_fc, g_ln, b_ln);
    k_mlp2<<<NROWS / 8, 256>>>(h_out, w_mlp2, b_mlp2, q_out);
}

// round 15
// speedup vs baseline: 1.1115x; 1.0023x over previous
#include <cuda_runtime.h>
#include <math.h>

#define NAg 8
#define Hdim 64
#define LATENT 512
#define NACT 14
#define BSZ 4096
#define NROWS 32768   // BSZ*NAg
#define LN0002 (-6.2146080984221914f)

typedef unsigned long long u64;

// ---- packed fp32x2 helpers ----
__device__ __forceinline__ u64 bc2(float x) {
    u64 r; asm("mov.b64 %0, {%1, %2};" : "=l"(r) : "f"(x), "f"(x)); return r;
}
__device__ __forceinline__ void fma2(u64& d, u64 a, u64 b) {
    asm("fma.rn.f32x2 %0, %1, %2, %3;" : "=l"(d) : "l"(a), "l"(b), "l"(d));
}
__device__ __forceinline__ float2 up2(u64 v) {
    float lo, hi; asm("mov.b64 {%0, %1}, %2;" : "=f"(lo), "=f"(hi) : "l"(v));
    return make_float2(lo, hi);
}
__device__ __forceinline__ u64 lds2(const float* p) { return *(const u64*)p; }
__device__ __forceinline__ float tanh_fast(float x) {
    float r; asm("tanh.approx.f32 %0, %1;" : "=f"(r) : "f"(x)); return r;
}
__device__ __forceinline__ float sigmoid_fast(float x) {
    return 1.f / (1.f + __expf(-x));
}

// ---------------- scratch ----------------
__device__ float g_uae[NROWS * 128];
__device__ float g_ae_acc[2 * 128];
__device__ float g_mean[NROWS * 512];
__device__ float g_lvar[NROWS * 512];
__device__ float g_aw[NROWS * 512];
__device__ float g_L[NROWS * 128];
__device__ float g_R[NROWS * 128];
__device__ float g_in_acc[5 * 128];
__device__ float g_att[NROWS * 512];

// ---------------- kernel A: fused mlp1 + GRU (+ accumulator zeroing) ----------------
__global__ __launch_bounds__(512) void k_mlp1_gru(
    const float* __restrict__ in, const float* __restrict__ hin,
    const float* __restrict__ W1, const float* __restrict__ b1,
    const float* __restrict__ Wih, const float* __restrict__ bih,
    const float* __restrict__ Whh, const float* __restrict__ bhh,
    float* __restrict__ hout)
{
    __shared__ float sInT[96][34];
    __shared__ float sXT[64][34];
    __shared__ float sHT[64][34];
    int tid = threadIdx.x;
    int row0 = blockIdx.x * 32;

    if (blockIdx.x == 0) {
        for (int i = tid; i < 256; i += 512) g_ae_acc[i] = 0.f;
        for (int i = tid; i < 640; i += 512) g_in_acc[i] = 0.f;
    }

    for (int idx = tid; idx < 32 * 96; idx += 512) {
        int r = idx / 96, k = idx % 96;
        sInT[k][r] = in[(row0 + r) * 96 + k];
    }
    for (int idx = tid; idx < 32 * 64; idx += 512) {
        int r = idx / 64, k = idx % 64;
        sHT[k][r] = hin[(row0 + r) * 64 + k];
    }
    __syncthreads();

    int c = tid & 63;
    int rg = tid >> 6;      // 0..7 -> rows rg*4..+3
    {
        u64 acc2[2] = {0ull, 0ull};
        for (int k = 0; k < 96; k++) {
            u64 w2 = bc2(W1[k * 64 + c]);
#pragma unroll
            for (int t = 0; t < 2; t++)
                fma2(acc2[t], lds2(&sInT[k][rg * 4 + 2 * t]), w2);
        }
        float b = b1[c];
#pragma unroll
        for (int t = 0; t < 2; t++) {
            float2 v = up2(acc2[t]);
            v.x += b; v.y += b;
            v.x = v.x > 0.f ? v.x : 0.f;
            v.y = v.y > 0.f ? v.y : 0.f;
            *(float2*)&sXT[c][rg * 4 + 2 * t] = v;
        }
    }
    __syncthreads();

    {
        int j = c;
        u64 axr2[2], axz2[2], axn2[2], ahr2[2], ahz2[2], ahn2[2];
#pragma unroll
        for (int t = 0; t < 2; t++) { axr2[t]=axz2[t]=axn2[t]=ahr2[t]=ahz2[t]=ahn2[t]=0ull; }
        for (int k = 0; k < 64; k++) {
            u64 wr = bc2(Wih[k * 192 + j]);
            u64 wz = bc2(Wih[k * 192 + 64 + j]);
            u64 wn = bc2(Wih[k * 192 + 128 + j]);
            u64 vr = bc2(Whh[k * 192 + j]);
            u64 vz = bc2(Whh[k * 192 + 64 + j]);
            u64 vn = bc2(Whh[k * 192 + 128 + j]);
#pragma unroll
            for (int t = 0; t < 2; t++) {
                u64 x2 = lds2(&sXT[k][rg * 4 + 2 * t]);
                u64 h2 = lds2(&sHT[k][rg * 4 + 2 * t]);
                fma2(axr2[t], x2, wr); fma2(axz2[t], x2, wz); fma2(axn2[t], x2, wn);
                fma2(ahr2[t], h2, vr); fma2(ahz2[t], h2, vz); fma2(ahn2[t], h2, vn);
            }
        }
        float br = bih[j], bz = bih[64 + j], bn_ = bih[128 + j];
        float cr = bhh[j], cz = bhh[64 + j], cn = bhh[128 + j];
#pragma unroll
        for (int t = 0; t < 2; t++) {
            float2 xr = up2(axr2[t]), xz = up2(axz2[t]), xn = up2(axn2[t]);
            float2 hr = up2(ahr2[t]), hz = up2(ahz2[t]), hn = up2(ahn2[t]);
#pragma unroll
            for (int lz = 0; lz < 2; lz++) {
                int r = rg * 4 + 2 * t + lz;
                float XR = lz ? xr.y : xr.x, XZ = lz ? xz.y : xz.x, XN = lz ? xn.y : xn.x;
                float HR = lz ? hr.y : hr.x, HZ = lz ? hz.y : hz.x, HN = lz ? hn.y : hn.x;
                float rg_ = sigmoid_fast((XR + br) + (HR + cr));
                float zg  = sigmoid_fast((XZ + bz) + (HZ + cz));
                float ng  = tanh_fast((XN + bn_) + rg_ * (HN + cn));
                float hprev = sHT[j][r];
                hout[(row0 + r) * 64 + j] = (1.f - zg) * ng + zg * hprev;
            }
        }
    }
}

// ---------------- kernel B: ae1 GEMM + column stats ----------------
__global__ void k_ae1(const float* __restrict__ hsrc,
                      const float* __restrict__ Wae1, const float* __restrict__ bae1)
{
    __shared__ float sHT[64][34];
    __shared__ float sred[256];
    int tid = threadIdx.x;
    int row0 = blockIdx.x * 32;
    for (int idx = tid; idx < 32 * 64; idx += 256) {
        int r = idx / 64, k = idx % 64;
        sHT[k][r] = hsrc[(row0 + r) * 64 + k];
    }
    __syncthreads();
    int c = tid & 127;
    int rg = tid >> 7;
    u64 acc2[8];
#pragma unroll
    for (int t = 0; t < 8; t++) acc2[t] = 0ull;
    for (int k = 0; k < 64; k++) {
        u64 w2 = bc2(Wae1[k * 128 + c]);
#pragma unroll
        for (int t = 0; t < 8; t++)
            fma2(acc2[t], lds2(&sHT[k][rg * 16 + 2 * t]), w2);
    }
    float b = bae1[c];
    float s = 0.f, q = 0.f;
#pragma unroll
    for (int t = 0; t < 8; t++) {
        float2 u2 = up2(acc2[t]);
        float u0 = u2.x + b, u1 = u2.y + b;
        g_uae[(row0 + rg * 16 + 2 * t) * 128 + c] = u0;
        g_uae[(row0 + rg * 16 + 2 * t + 1) * 128 + c] = u1;
        s += u0 + u1; q += u0 * u0 + u1 * u1;
    }
    sred[tid] = s; __syncthreads();
    if (tid < 128) atomicAdd(&g_ae_acc[tid], sred[tid] + sred[tid + 128]);
    __syncthreads();
    sred[tid] = q; __syncthreads();
    if (tid < 128) atomicAdd(&g_ae_acc[128 + tid], sred[tid] + sred[tid + 128]);
}

// ---------------- kernel D: ae2 GEMM (R10 form: transposed sUT stride 34) ----------------
__global__ __launch_bounds__(256) void k_ae2(
    const float* __restrict__ Wae2, const float* __restrict__ bae2,
    const float* __restrict__ noise,
    const float* __restrict__ gae, const float* __restrict__ beae)
{
    __shared__ float sUT[128 * 34];
    __shared__ float s_sc[128], s_sh[128];
    int tid = threadIdx.x;
    int row0 = blockIdx.x * 32;
    int p = blockIdx.y;

    if (tid < 128) {
        float m = g_ae_acc[tid] * (1.f / 32768.f);
        float var = g_ae_acc[128 + tid] * (1.f / 32768.f) - m * m;
        float s = rsqrtf(var + 1e-5f) * gae[tid];
        s_sc[tid] = s;
        s_sh[tid] = beae[tid] - m * s;
    }
    __syncthreads();

    for (int idx = tid; idx < 32 * 128; idx += 256) {
        int r = idx >> 7, k = idx & 127;
        float u = g_uae[(size_t)row0 * 128 + idx];
        float v = u * s_sc[k] + s_sh[k];
        sUT[k * 34 + r] = v >= 0.f ? v : 0.01f * v;
    }
    __syncthreads();

    int rg = tid >> 5;
    int cg = tid & 31;
    int cm = p * 128 + cg * 4;
    int cv = 512 + cm;
    u64 acc2[2][8];
#pragma unroll
    for (int t = 0; t < 2; t++)
#pragma unroll
        for (int c = 0; c < 8; c++) acc2[t][c] = 0ull;

    for (int k = 0; k < 128; k++) {
        float4 wm = *(const float4*)&Wae2[k * 1024 + cm];
        float4 wv = *(const float4*)&Wae2[k * 1024 + cv];
        u64 wb[8];
        wb[0] = bc2(wm.x); wb[1] = bc2(wm.y); wb[2] = bc2(wm.z); wb[3] = bc2(wm.w);
        wb[4] = bc2(wv.x); wb[5] = bc2(wv.y); wb[6] = bc2(wv.z); wb[7] = bc2(wv.w);
#pragma unroll
        for (int t = 0; t < 2; t++) {
            u64 u2 = lds2(&sUT[k * 34 + rg * 4 + 2 * t]);
#pragma unroll
            for (int c = 0; c < 8; c++) fma2(acc2[t][c], u2, wb[c]);
        }
    }
    float4 bm = *(const float4*)&bae2[cm];
    float4 bv = *(const float4*)&bae2[cv];
#pragma unroll
    for (int t = 0; t < 2; t++) {
        float2 c0 = up2(acc2[t][0]), c1 = up2(acc2[t][1]);
        float2 c2 = up2(acc2[t][2]), c3 = up2(acc2[t][3]);
        float2 v0 = up2(acc2[t][4]), v1 = up2(acc2[t][5]);
        float2 v2 = up2(acc2[t][6]), v3 = up2(acc2[t][7]);
#pragma unroll
        for (int lz = 0; lz < 2; lz++) {
            size_t row = row0 + rg * 4 + 2 * t + lz;
            float m0 = (lz ? c0.y : c0.x) + bm.x;
            float m1 = (lz ? c1.y : c1.x) + bm.y;
            float m2 = (lz ? c2.y : c2.x) + bm.z;
            float m3 = (lz ? c3.y : c3.x) + bm.w;
            float l0 = fmaxf((lz ? v0.y : v0.x) + bv.x, LN0002);
            float l1 = fmaxf((lz ? v1.y : v1.x) + bv.y, LN0002);
            float l2 = fmaxf((lz ? v2.y : v2.x) + bv.z, LN0002);
            float l3 = fmaxf((lz ? v3.y : v3.x) + bv.w, LN0002);
            size_t off = row * 512 + cm;
            float4 nz = *(const float4*)&noise[off];
            *(float4*)&g_mean[off] = make_float4(m0, m1, m2, m3);
            *(float4*)&g_lvar[off] = make_float4(l0, l1, l2, l3);
            *(float4*)&g_aw[off]   = make_float4(m0 + __expf(0.5f * l0) * nz.x,
                                                 m1 + __expf(0.5f * l1) * nz.y,
                                                 m2 + __expf(0.5f * l2) * nz.z,
                                                 m3 + __expf(0.5f * l3) * nz.w);
        }
    }
}

// ---------------- kernel K: fused MHA + layernorm -> g_att (launch slot 3) ----------------
#define QPS 133
#define VPS 144
#define OPS 132
#define FPS 67
#define OFF_A   0
#define OFF_Q   2048
#define OFF_K   6304
#define OFF_V   10560
#define OFF_P   15168
#define OFF_O   16320
#define OFF_F   20544
#define OFF_MU  22688
#define OFF_RS  22720
#define ATTN_SMEM_FLOATS 22752

__global__ __launch_bounds__(512) void k_attn(
    const float* __restrict__ wq, const float* __restrict__ wk,
    const float* __restrict__ wv,
    const float* __restrict__ wfc,
    const float* __restrict__ gln, const float* __restrict__ bln)
{
    extern __shared__ float sm[];
    float* sA  = sm + OFF_A;
    float* sQp = sm + OFF_Q;
    float* sKp = sm + OFF_K;
    float* sVp = sm + OFF_V;
    float* sP  = sm + OFF_P;
    float* sO  = sm + OFF_O;
    float* sF  = sm + OFF_F;
    float* sMu = sm + OFF_MU;
    float* sRs = sm + OFF_RS;

    int tid = threadIdx.x;
    int w = tid >> 5;
    int lane = tid & 31;

    size_t base = (size_t)blockIdx.x * 2048;
    for (int idx = tid; idx < 2048; idx += 512) sA[idx] = g_aw[base + idx];
    __syncthreads();

    // ---- QKV projections (weights direct from wq/wk/wv) ----
    {
        int r0 = w * 2, r1 = r0 + 1;
        int cl = lane * 4;
        int h = cl >> 5, within = cl & 31;
        const float* ar0 = sA + r0 * 64;
        const float* ar1 = sA + r1 * 64;
#pragma unroll
        for (int pass = 0; pass < 3; pass++) {
            const float* wsel = (pass == 0) ? wq : (pass == 1) ? wk : wv;
            u64 a0p[2] = {0ull, 0ull}, a1p[2] = {0ull, 0ull};
            const float* wp = wsel + cl;
#pragma unroll 4
            for (int k = 0; k < 64; k++) {
                ulonglong2 w4 = *(const ulonglong2*)&wp[k * 128];
                u64 a0 = bc2(ar0[k]), a1 = bc2(ar1[k]);
                fma2(a0p[0], a0, w4.x); fma2(a0p[1], a0, w4.y);
                fma2(a1p[0], a1, w4.x); fma2(a1p[1], a1, w4.y);
            }
            float2 q001 = up2(a0p[0]), q023 = up2(a0p[1]);
            float2 q101 = up2(a1p[0]), q123 = up2(a1p[1]);
            if (pass < 2) {
                float* dst = (pass == 0) ? sQp : sKp;
                int pc = h * 33 + within;
                dst[r0 * QPS + pc]     = q001.x; dst[r0 * QPS + pc + 1] = q001.y;
                dst[r0 * QPS + pc + 2] = q023.x; dst[r0 * QPS + pc + 3] = q023.y;
                dst[r1 * QPS + pc]     = q101.x; dst[r1 * QPS + pc + 1] = q101.y;
                dst[r1 * QPS + pc + 2] = q123.x; dst[r1 * QPS + pc + 3] = q123.y;
            } else {
                int pc = h * 36 + within;
                *(float4*)&sVp[r0 * VPS + pc] = make_float4(q001.x, q001.y, q023.x, q023.y);
                *(float4*)&sVp[r1 * VPS + pc] = make_float4(q101.x, q101.y, q123.x, q123.y);
            }
        }
    }
    __syncthreads();

    // ---- scores + softmax ----
    {
        int b = w >> 2, h = w & 3;
        int s = lane & 7, dgrp = lane >> 3;
        const float* qb = sQp + (b * 8 + s) * QPS + h * 33 + dgrp * 8;
        float q[8];
#pragma unroll
        for (int d = 0; d < 8; d++) q[d] = qb[d];
        float scv[8];
#pragma unroll
        for (int u = 0; u < 8; u++) {
            const float* kr = sKp + (b * 8 + u) * QPS + h * 33 + dgrp * 8;
            float p = 0.f;
#pragma unroll
            for (int d = 0; d < 8; d++) p += q[d] * kr[d];
            scv[u] = p;
        }
#pragma unroll
        for (int u = 0; u < 8; u++) {
            scv[u] += __shfl_xor_sync(0xffffffffu, scv[u], 8);
            scv[u] += __shfl_xor_sync(0xffffffffu, scv[u], 16);
        }
        if (lane < 8) {
            float mx = -1e30f;
#pragma unroll
            for (int u = 0; u < 8; u++) {
                scv[u] *= 0.17677669529663687f;
                mx = fmaxf(mx, scv[u]);
            }
            float sum = 0.f;
#pragma unroll
            for (int u = 0; u < 8; u++) { scv[u] = __expf(scv[u] - mx); sum += scv[u]; }
            float inv = 1.f / sum;
            float* pr = sP + ((b * 4 + h) * 8 + s) * 9;
#pragma unroll
            for (int u = 0; u < 8; u++) pr[u] = scv[u] * inv;
        }
    }
    __syncthreads();

    // ---- O = P @ V ----
    {
        int b = w >> 2;
        int s0 = (w & 3) * 2, s1 = s0 + 1;
        int c0 = lane * 4;
        int h = c0 >> 5;
        int pc = h * 36 + (c0 & 31);
        float o0[4], o1[4];
#pragma unroll
        for (int t = 0; t < 4; t++) { o0[t] = 0.f; o1[t] = 0.f; }
#pragma unroll
        for (int u = 0; u < 8; u++) {
            float4 v4 = *(const float4*)&sVp[(b * 8 + u) * VPS + pc];
            float p0 = sP[((b * 4 + h) * 8 + s0) * 9 + u];
            float p1 = sP[((b * 4 + h) * 8 + s1) * 9 + u];
            o0[0] += p0 * v4.x; o0[1] += p0 * v4.y; o0[2] += p0 * v4.z; o0[3] += p0 * v4.w;
            o1[0] += p1 * v4.x; o1[1] += p1 * v4.y; o1[2] += p1 * v4.z; o1[3] += p1 * v4.w;
        }
        *(float4*)&sO[(b * 8 + s0) * OPS + c0] = make_float4(o0[0], o0[1], o0[2], o0[3]);
        *(float4*)&sO[(b * 8 + s1) * OPS + c0] = make_float4(o1[0], o1[1], o1[2], o1[3]);
    }
    __syncthreads();

    // ---- fc + residual ----
    {
        int r0 = w * 2, r1 = r0 + 1;
        int c0 = lane * 2;
        u64 p0 = 0ull, p1 = 0ull;
        const float* o0 = sO + r0 * OPS;
        const float* o1 = sO + r1 * OPS;
#pragma unroll 4
        for (int k = 0; k < 128; k++) {
            u64 w2 = *(const u64*)&wfc[k * 64 + c0];
            fma2(p0, bc2(o0[k]), w2);
            fma2(p1, bc2(o1[k]), w2);
        }
        float2 f0 = up2(p0), f1 = up2(p1);
        sF[r0 * FPS + c0]     = f0.x + sA[r0 * 64 + c0];
        sF[r0 * FPS + c0 + 1] = f0.y + sA[r0 * 64 + c0 + 1];
        sF[r1 * FPS + c0]     = f1.x + sA[r1 * 64 + c0];
        sF[r1 * FPS + c0 + 1] = f1.y + sA[r1 * 64 + c0 + 1];
    }
    __syncthreads();

    if (tid < 32) {
        const float* fr = sF + tid * FPS;
        float m = 0.f;
#pragma unroll
        for (int c = 0; c < 64; c++) m += fr[c];
        m *= (1.f / 64.f);
        float v = 0.f;
#pragma unroll
        for (int c = 0; c < 64; c++) { float d = fr[c] - m; v += d * d; }
        v *= (1.f / 64.f);
        sMu[tid] = m;
        sRs[tid] = rsqrtf(v + 1e-6f);
    }
    __syncthreads();

    for (int idx = tid; idx < 2048; idx += 512) {
        int r = idx >> 6, c = idx & 63;
        g_att[base + idx] = (sF[r * FPS + c] - sMu[r]) * sRs[r] * gln[c] + bln[c];
    }
}

// ---------------- kernel F: L/R GEMMs + column stats ----------------
__global__ void k_LR(const float* __restrict__ hsrc, const float* __restrict__ Win1)
{
    __shared__ float sHT[64][34];
    int tid = threadIdx.x;
    int row0 = blockIdx.x * 32;
    for (int idx = tid; idx < 32 * 64; idx += 256) {
        int r = idx / 64, k = idx % 64;
        sHT[k][r] = hsrc[(row0 + r) * 64 + k];
    }
    __syncthreads();
    int cc = tid;
    int cm = cc & 127;
    u64 acc2[16];
#pragma unroll
    for (int t = 0; t < 16; t++) acc2[t] = 0ull;
    for (int k = 0; k < 64; k++) {
        float w = (cc < 128) ? Win1[k * 128 + cm] : Win1[(64 + k) * 128 + cm];
        u64 w2 = bc2(w);
#pragma unroll
        for (int t = 0; t < 16; t++)
            fma2(acc2[t], lds2(&sHT[k][2 * t]), w2);
    }
    float* dst = (cc < 128) ? g_L : g_R;
    float s = 0.f, q = 0.f;
#pragma unroll
    for (int t = 0; t < 16; t++) {
        float2 v2 = up2(acc2[t]);
        dst[(row0 + 2 * t) * 128 + cm] = v2.x;
        dst[(row0 + 2 * t + 1) * 128 + cm] = v2.y;
        s += v2.x + v2.y; q += v2.x * v2.x + v2.y * v2.y;
    }
    atomicAdd(&g_in_acc[cc], s);
    atomicAdd(&g_in_acc[256 + cc], q);
}

__global__ void k_cross() {
    __shared__ float sred[256];
    int tid = threadIdx.x;
    int c = tid & 127;
    int bg = tid >> 7;
    int b0 = blockIdx.x * 32;
    float cr = 0.f;
    for (int bb = bg * 16; bb < bg * 16 + 16; bb++) {
        int b = b0 + bb;
        float sl = 0.f, sr = 0.f;
#pragma unroll
        for (int i = 0; i < 8; i++) {
            sl += g_L[(b * 8 + i) * 128 + c];
            sr += g_R[(b * 8 + i) * 128 + c];
        }
        cr += sl * sr;
    }
    sred[tid] = cr; __syncthreads();
    if (tid < 128) atomicAdd(&g_in_acc[512 + tid], sred[tid] + sred[tid + 128]);
}

// ---------------- kernel I: infer GEMM + KLD (R12 form) ----------------
__global__ __launch_bounds__(256) void k_infer(
    const float* __restrict__ Win2, const float* __restrict__ bin2,
    const float* __restrict__ bin1,
    const float* __restrict__ gin, const float* __restrict__ bein,
    float* __restrict__ kld_out)
{
    __shared__ float sL[8 * 128], sR[8 * 128];
    __shared__ __align__(16) float sUT[128 * 36];
    __shared__ float sIP[32 * 128];
    __shared__ float s_sc[128], s_sh[128];
    __shared__ float sred[256];
    int b = blockIdx.x;
    int tid = threadIdx.x;
    for (int idx = tid; idx < 1024; idx += 256) {
        sL[idx] = g_L[(size_t)b * 1024 + idx];
        sR[idx] = g_R[(size_t)b * 1024 + idx];
    }
    if (tid < 128) {
        int c = tid;
        float sl = g_in_acc[c], sr = g_in_acc[128 + c];
        float ql = g_in_acc[256 + c], qr = g_in_acc[384 + c];
        float cr = g_in_acc[512 + c];
        float beta = bin1[c];
        const float Nr = 262144.f;
        float mean = 8.f * (sl + sr) / Nr + beta;
        float e2 = (8.f * ql + 8.f * qr + 2.f * cr + 16.f * beta * (sl + sr)) / Nr + beta * beta;
        float var = e2 - mean * mean;
        float s = rsqrtf(var + 1e-5f) * gin[c];
        s_sc[c] = s;
        s_sh[c] = bein[c] + (beta - mean) * s;
    }
    __syncthreads();

    int wr = tid >> 5;
    int cg = tid & 31;
    float4 bia = *(const float4*)&bin2[cg * 4];
    float kacc = 0.f;

    for (int half = 0; half < 2; half++) {
        int i0 = half * 4;
        for (int idx = tid; idx < 4096; idx += 256) {
            int r = idx >> 7, k = idx & 127;
            int ii = r >> 3, j = r & 7;
            float v = (sL[(i0 + ii) * 128 + k] + sR[j * 128 + k]) * s_sc[k] + s_sh[k];
            sUT[k * 36 + r] = v >= 0.f ? v : 0.01f * v;
        }
        __syncthreads();
        u64 acc2[4][2];
#pragma unroll
        for (int i = 0; i < 4; i++) { acc2[i][0] = 0ull; acc2[i][1] = 0ull; }
        for (int k = 0; k < 128; k++) {
            float4 a4 = *(const float4*)&sUT[k * 36 + wr * 4];
            ulonglong2 w = *(const ulonglong2*)&Win2[k * 128 + cg * 4];
            u64 b0 = bc2(a4.x), b1 = bc2(a4.y), b2 = bc2(a4.z), b3 = bc2(a4.w);
            fma2(acc2[0][0], b0, w.x); fma2(acc2[0][1], b0, w.y);
            fma2(acc2[1][0], b1, w.x); fma2(acc2[1][1], b1, w.y);
            fma2(acc2[2][0], b2, w.x); fma2(acc2[2][1], b2, w.y);
            fma2(acc2[3][0], b3, w.x); fma2(acc2[3][1], b3, w.y);
        }
#pragma unroll
        for (int i = 0; i < 4; i++) {
            float2 a01 = up2(acc2[i][0]), a23 = up2(acc2[i][1]);
            *(float4*)&sIP[(wr * 4 + i) * 128 + cg * 4] =
                make_float4(a01.x + bia.x, a01.y + bia.y, a23.x + bia.z, a23.y + bia.w);
        }
        __syncthreads();
        for (int ii = 0; ii < 4; ii++) {
            const float* mrow = g_mean + (size_t)(b * 8 + i0 + ii) * 512;
            const float* vrow = g_lvar + (size_t)(b * 8 + i0 + ii) * 512;
            for (int idx = tid; idx < 512; idx += 256) {
                int j = idx >> 6, d = idx & 63;
                float im  = sIP[(ii * 8 + j) * 128 + d];
                float liv = fmaxf(sIP[(ii * 8 + j) * 128 + 64 + d], LN0002);
                float riv = __expf(-liv);
                float lv  = vrow[idx];
                float v0  = __expf(lv);
                float dm  = mrow[idx] - im;
                kacc += 0.5f * (liv - lv) + 0.5f * (v0 + dm * dm) * riv - 0.5f;
            }
        }
        __syncthreads();
    }
    sred[tid] = kacc; __syncthreads();
    for (int s = 128; s > 0; s >>= 1) {
        if (tid < s) sred[tid] += sred[tid + s];
        __syncthreads();
    }
    if (tid == 0) kld_out[b] = sred[0] * (1.f / 4096.f);
}

// ---------------- kernel L: mlp2 ----------------
__global__ void k_mlp2(const float* __restrict__ hsrc,
                       const float* __restrict__ W2, const float* __restrict__ b2,
                       float* __restrict__ qout)
{
    __shared__ float sWt[14 * 576];
    int tid = threadIdx.x;
    for (int idx = tid; idx < 14 * 576; idx += 256) {
        int c = idx / 576, k = idx % 576;
        sWt[c * 576 + k] = W2[k * 14 + c];
    }
    __syncthreads();
    int w = tid >> 5, l = tid & 31;
    size_t row = (size_t)blockIdx.x * 8 + w;
    const float* hr = hsrc + row * 64;
    const float* ar = g_att + row * 512;
    float acc[14];
#pragma unroll
    for (int c = 0; c < 14; c++) acc[c] = 0.f;
    for (int k = l; k < 576; k += 32) {
        float v = (k < 64) ? hr[k] : ar[k - 64];
#pragma unroll
        for (int c = 0; c < 14; c++) acc[c] += v * sWt[c * 576 + k];
    }
#pragma unroll
    for (int c = 0; c < 14; c++) {
        float a = acc[c];
        for (int o = 16; o > 0; o >>= 1) a += __shfl_down_sync(0xffffffffu, a, o);
        if (l == 0) qout[row * 14 + c] = a + b2[c];
    }
}

// ---------------- launch ----------------
extern "C" void kernel_launch(void* const* d_in, const int* in_sizes, int n_in,
                              void* d_out, int out_size)
{
    const float* inputs = (const float*)d_in[0];
    const float* hidden = (const float*)d_in[1];
    const float* noise  = (const float*)d_in[2];
    const float* w_mlp1 = (const float*)d_in[3];
    const float* b_mlp1 = (const float*)d_in[4];
    const float* w_ih   = (const float*)d_in[5];
    const float* b_ih   = (const float*)d_in[6];
    const float* w_hh   = (const float*)d_in[7];
    const float* b_hh   = (const float*)d_in[8];
    const float* w_ae1  = (const float*)d_in[9];
    const float* b_ae1  = (const float*)d_in[10];
    const float* g_ae   = (const float*)d_in[11];
    const float* be_ae  = (const float*)d_in[12];
    const float* w_ae2  = (const float*)d_in[13];
    const float* b_ae2  = (const float*)d_in[14];
    const float* w_in1  = (const float*)d_in[15];
    const float* b_in1  = (const float*)d_in[16];
    const float* g_in   = (const float*)d_in[17];
    const float* be_in  = (const float*)d_in[18];
    const float* w_in2  = (const float*)d_in[19];
    const float* b_in2  = (const float*)d_in[20];
    const float* w_q    = (const float*)d_in[21];
    const float* w_k    = (const float*)d_in[22];
    const float* w_v    = (const float*)d_in[23];
    const float* w_fc   = (const float*)d_in[24];
    const float* g_ln   = (const float*)d_in[25];
    const float* b_ln   = (const float*)d_in[26];
    const float* w_mlp2 = (const float*)d_in[27];
    const float* b_mlp2 = (const float*)d_in[28];

    float* out = (float*)d_out;
    float* q_out   = out;
    float* h_out   = out + NROWS * NACT;
    float* kld_out = h_out + NROWS * Hdim;

    static int attn_smem_set = 0;
    const int ATTN_SMEM = ATTN_SMEM_FLOATS * 4;
    if (!attn_smem_set) {
        cudaFuncSetAttribute(k_attn, cudaFuncAttributeMaxDynamicSharedMemorySize, ATTN_SMEM);
        attn_smem_set = 1;
    }

    // launch index 3 (k_attn) is the ncu capture slot
    k_mlp1_gru<<<NROWS / 32, 512>>>(inputs, hidden, w_mlp1, b_mlp1, w_ih, b_ih, w_hh, b_hh, h_out);
    k_ae1<<<NROWS / 32, 256>>>(h_out, w_ae1, b_ae1);
    k_ae2<<<dim3(NROWS / 32, 4), 256>>>(w_ae2, b_ae2, noise, g_ae, be_ae);
    k_attn<<<NROWS / 4, 512, ATTN_SMEM>>>(w_q, w_k, w_v, w_fc, g_ln, b_ln);
    k_LR<<<NROWS / 32, 256>>>(h_out, w_in1);
    k_cross<<<BSZ / 32, 256>>>();
    k_infer<<<BSZ, 256>>>(w_in2, b_in2, b_in1, g_in, be_in, kld_out);
    k_mlp2<<<NROWS / 8, 256>>>(h_out, w_mlp2, b_mlp2, q_out);
}

// round 16
// speedup vs baseline: 1.2183x; 1.0962x over previous
#include <cuda_runtime.h>
#include <math.h>

#define NAg 8
#define Hdim 64
#define LATENT 512
#define NACT 14
#define BSZ 4096
#define NROWS 32768   // BSZ*NAg
#define LN0002 (-6.2146080984221914f)

typedef unsigned long long u64;

// ---- packed fp32x2 helpers ----
__device__ __forceinline__ u64 bc2(float x) {
    u64 r; asm("mov.b64 %0, {%1, %2};" : "=l"(r) : "f"(x), "f"(x)); return r;
}
__device__ __forceinline__ void fma2(u64& d, u64 a, u64 b) {
    asm("fma.rn.f32x2 %0, %1, %2, %3;" : "=l"(d) : "l"(a), "l"(b), "l"(d));
}
__device__ __forceinline__ float2 up2(u64 v) {
    float lo, hi; asm("mov.b64 {%0, %1}, %2;" : "=f"(lo), "=f"(hi) : "l"(v));
    return make_float2(lo, hi);
}
__device__ __forceinline__ u64 lds2(const float* p) { return *(const u64*)p; }
__device__ __forceinline__ float tanh_fast(float x) {
    float r; asm("tanh.approx.f32 %0, %1;" : "=f"(r) : "f"(x)); return r;
}
__device__ __forceinline__ float sigmoid_fast(float x) {
    return 1.f / (1.f + __expf(-x));
}

// ---------------- scratch ----------------
__device__ float g_uae[NROWS * 128];
__device__ float g_ae_acc[2 * 128];
__device__ float g_mean[NROWS * 512];
__device__ float g_lvar[NROWS * 512];
__device__ float g_aw[NROWS * 512];
__device__ float g_L[NROWS * 128];
__device__ float g_R[NROWS * 128];
__device__ float g_in_acc[5 * 128];
__device__ float g_att[NROWS * 512];

// ---------------- kernel A: fused mlp1 + GRU (+ accumulator zeroing) ----------------
__global__ __launch_bounds__(512) void k_mlp1_gru(
    const float* __restrict__ in, const float* __restrict__ hin,
    const float* __restrict__ W1, const float* __restrict__ b1,
    const float* __restrict__ Wih, const float* __restrict__ bih,
    const float* __restrict__ Whh, const float* __restrict__ bhh,
    float* __restrict__ hout)
{
    __shared__ float sInT[96][34];
    __shared__ float sXT[64][34];
    __shared__ float sHT[64][34];
    int tid = threadIdx.x;
    int row0 = blockIdx.x * 32;

    if (blockIdx.x == 0) {
        for (int i = tid; i < 256; i += 512) g_ae_acc[i] = 0.f;
        for (int i = tid; i < 640; i += 512) g_in_acc[i] = 0.f;
    }

    for (int idx = tid; idx < 32 * 96; idx += 512) {
        int r = idx / 96, k = idx % 96;
        sInT[k][r] = in[(row0 + r) * 96 + k];
    }
    for (int idx = tid; idx < 32 * 64; idx += 512) {
        int r = idx / 64, k = idx % 64;
        sHT[k][r] = hin[(row0 + r) * 64 + k];
    }
    __syncthreads();

    int c = tid & 63;
    int rg = tid >> 6;      // 0..7 -> rows rg*4..+3
    {
        u64 acc2[2] = {0ull, 0ull};
        for (int k = 0; k < 96; k++) {
            u64 w2 = bc2(W1[k * 64 + c]);
#pragma unroll
            for (int t = 0; t < 2; t++)
                fma2(acc2[t], lds2(&sInT[k][rg * 4 + 2 * t]), w2);
        }
        float b = b1[c];
#pragma unroll
        for (int t = 0; t < 2; t++) {
            float2 v = up2(acc2[t]);
            v.x += b; v.y += b;
            v.x = v.x > 0.f ? v.x : 0.f;
            v.y = v.y > 0.f ? v.y : 0.f;
            *(float2*)&sXT[c][rg * 4 + 2 * t] = v;
        }
    }
    __syncthreads();

    {
        int j = c;
        u64 axr2[2], axz2[2], axn2[2], ahr2[2], ahz2[2], ahn2[2];
#pragma unroll
        for (int t = 0; t < 2; t++) { axr2[t]=axz2[t]=axn2[t]=ahr2[t]=ahz2[t]=ahn2[t]=0ull; }
        for (int k = 0; k < 64; k++) {
            u64 wr = bc2(Wih[k * 192 + j]);
            u64 wz = bc2(Wih[k * 192 + 64 + j]);
            u64 wn = bc2(Wih[k * 192 + 128 + j]);
            u64 vr = bc2(Whh[k * 192 + j]);
            u64 vz = bc2(Whh[k * 192 + 64 + j]);
            u64 vn = bc2(Whh[k * 192 + 128 + j]);
#pragma unroll
            for (int t = 0; t < 2; t++) {
                u64 x2 = lds2(&sXT[k][rg * 4 + 2 * t]);
                u64 h2 = lds2(&sHT[k][rg * 4 + 2 * t]);
                fma2(axr2[t], x2, wr); fma2(axz2[t], x2, wz); fma2(axn2[t], x2, wn);
                fma2(ahr2[t], h2, vr); fma2(ahz2[t], h2, vz); fma2(ahn2[t], h2, vn);
            }
        }
        float br = bih[j], bz = bih[64 + j], bn_ = bih[128 + j];
        float cr = bhh[j], cz = bhh[64 + j], cn = bhh[128 + j];
#pragma unroll
        for (int t = 0; t < 2; t++) {
            float2 xr = up2(axr2[t]), xz = up2(axz2[t]), xn = up2(axn2[t]);
            float2 hr = up2(ahr2[t]), hz = up2(ahz2[t]), hn = up2(ahn2[t]);
#pragma unroll
            for (int lz = 0; lz < 2; lz++) {
                int r = rg * 4 + 2 * t + lz;
                float XR = lz ? xr.y : xr.x, XZ = lz ? xz.y : xz.x, XN = lz ? xn.y : xn.x;
                float HR = lz ? hr.y : hr.x, HZ = lz ? hz.y : hz.x, HN = lz ? hn.y : hn.x;
                float rg_ = sigmoid_fast((XR + br) + (HR + cr));
                float zg  = sigmoid_fast((XZ + bz) + (HZ + cz));
                float ng  = tanh_fast((XN + bn_) + rg_ * (HN + cn));
                float hprev = sHT[j][r];
                hout[(row0 + r) * 64 + j] = (1.f - zg) * ng + zg * hprev;
            }
        }
    }
}

// ---------------- kernel B: ae1 GEMM + column stats ----------------
__global__ void k_ae1(const float* __restrict__ hsrc,
                      const float* __restrict__ Wae1, const float* __restrict__ bae1)
{
    __shared__ float sHT[64][34];
    __shared__ float sred[256];
    int tid = threadIdx.x;
    int row0 = blockIdx.x * 32;
    for (int idx = tid; idx < 32 * 64; idx += 256) {
        int r = idx / 64, k = idx % 64;
        sHT[k][r] = hsrc[(row0 + r) * 64 + k];
    }
    __syncthreads();
    int c = tid & 127;
    int rg = tid >> 7;
    u64 acc2[8];
#pragma unroll
    for (int t = 0; t < 8; t++) acc2[t] = 0ull;
    for (int k = 0; k < 64; k++) {
        u64 w2 = bc2(Wae1[k * 128 + c]);
#pragma unroll
        for (int t = 0; t < 8; t++)
            fma2(acc2[t], lds2(&sHT[k][rg * 16 + 2 * t]), w2);
    }
    float b = bae1[c];
    float s = 0.f, q = 0.f;
#pragma unroll
    for (int t = 0; t < 8; t++) {
        float2 u2 = up2(acc2[t]);
        float u0 = u2.x + b, u1 = u2.y + b;
        g_uae[(row0 + rg * 16 + 2 * t) * 128 + c] = u0;
        g_uae[(row0 + rg * 16 + 2 * t + 1) * 128 + c] = u1;
        s += u0 + u1; q += u0 * u0 + u1 * u1;
    }
    sred[tid] = s; __syncthreads();
    if (tid < 128) atomicAdd(&g_ae_acc[tid], sred[tid] + sred[tid + 128]);
    __syncthreads();
    sred[tid] = q; __syncthreads();
    if (tid < 128) atomicAdd(&g_ae_acc[128 + tid], sred[tid] + sred[tid + 128]);
}

// ---------------- kernel D: ae2 GEMM (R10 form: transposed sUT stride 34) ----------------
__global__ __launch_bounds__(256) void k_ae2(
    const float* __restrict__ Wae2, const float* __restrict__ bae2,
    const float* __restrict__ noise,
    const float* __restrict__ gae, const float* __restrict__ beae)
{
    __shared__ float sUT[128 * 34];
    __shared__ float s_sc[128], s_sh[128];
    int tid = threadIdx.x;
    int row0 = blockIdx.x * 32;
    int p = blockIdx.y;

    if (tid < 128) {
        float m = g_ae_acc[tid] * (1.f / 32768.f);
        float var = g_ae_acc[128 + tid] * (1.f / 32768.f) - m * m;
        float s = rsqrtf(var + 1e-5f) * gae[tid];
        s_sc[tid] = s;
        s_sh[tid] = beae[tid] - m * s;
    }
    __syncthreads();

    for (int idx = tid; idx < 32 * 128; idx += 256) {
        int r = idx >> 7, k = idx & 127;
        float u = g_uae[(size_t)row0 * 128 + idx];
        float v = u * s_sc[k] + s_sh[k];
        sUT[k * 34 + r] = v >= 0.f ? v : 0.01f * v;
    }
    __syncthreads();

    int rg = tid >> 5;
    int cg = tid & 31;
    int cm = p * 128 + cg * 4;
    int cv = 512 + cm;
    u64 acc2[2][8];
#pragma unroll
    for (int t = 0; t < 2; t++)
#pragma unroll
        for (int c = 0; c < 8; c++) acc2[t][c] = 0ull;

    for (int k = 0; k < 128; k++) {
        float4 wm = *(const float4*)&Wae2[k * 1024 + cm];
        float4 wv = *(const float4*)&Wae2[k * 1024 + cv];
        u64 wb[8];
        wb[0] = bc2(wm.x); wb[1] = bc2(wm.y); wb[2] = bc2(wm.z); wb[3] = bc2(wm.w);
        wb[4] = bc2(wv.x); wb[5] = bc2(wv.y); wb[6] = bc2(wv.z); wb[7] = bc2(wv.w);
#pragma unroll
        for (int t = 0; t < 2; t++) {
            u64 u2 = lds2(&sUT[k * 34 + rg * 4 + 2 * t]);
#pragma unroll
            for (int c = 0; c < 8; c++) fma2(acc2[t][c], u2, wb[c]);
        }
    }
    float4 bm = *(const float4*)&bae2[cm];
    float4 bv = *(const float4*)&bae2[cv];
#pragma unroll
    for (int t = 0; t < 2; t++) {
        float2 c0 = up2(acc2[t][0]), c1 = up2(acc2[t][1]);
        float2 c2 = up2(acc2[t][2]), c3 = up2(acc2[t][3]);
        float2 v0 = up2(acc2[t][4]), v1 = up2(acc2[t][5]);
        float2 v2 = up2(acc2[t][6]), v3 = up2(acc2[t][7]);
#pragma unroll
        for (int lz = 0; lz < 2; lz++) {
            size_t row = row0 + rg * 4 + 2 * t + lz;
            float m0 = (lz ? c0.y : c0.x) + bm.x;
            float m1 = (lz ? c1.y : c1.x) + bm.y;
            float m2 = (lz ? c2.y : c2.x) + bm.z;
            float m3 = (lz ? c3.y : c3.x) + bm.w;
            float l0 = fmaxf((lz ? v0.y : v0.x) + bv.x, LN0002);
            float l1 = fmaxf((lz ? v1.y : v1.x) + bv.y, LN0002);
            float l2 = fmaxf((lz ? v2.y : v2.x) + bv.z, LN0002);
            float l3 = fmaxf((lz ? v3.y : v3.x) + bv.w, LN0002);
            size_t off = row * 512 + cm;
            float4 nz = *(const float4*)&noise[off];
            *(float4*)&g_mean[off] = make_float4(m0, m1, m2, m3);
            *(float4*)&g_lvar[off] = make_float4(l0, l1, l2, l3);
            *(float4*)&g_aw[off]   = make_float4(m0 + __expf(0.5f * l0) * nz.x,
                                                 m1 + __expf(0.5f * l1) * nz.y,
                                                 m2 + __expf(0.5f * l2) * nz.z,
                                                 m3 + __expf(0.5f * l3) * nz.w);
        }
    }
}

// ---------------- kernel K: fused MHA + layernorm -> g_att (launch slot 3) ----------------
// __launch_bounds__(512, 2): regs were 70 -> 1 CTA/SM (reg-limited). Cap at 64
// regs to get 2 CTA/SM (occ 25% -> 50%).
#define QPS 133
#define VPS 144
#define OPS 132
#define FPS 67
#define OFF_A   0
#define OFF_Q   2048
#define OFF_K   6304
#define OFF_V   10560
#define OFF_P   15168
#define OFF_O   16320
#define OFF_F   20544
#define OFF_MU  22688
#define OFF_RS  22720
#define ATTN_SMEM_FLOATS 22752

__global__ __launch_bounds__(512, 2) void k_attn(
    const float* __restrict__ wq, const float* __restrict__ wk,
    const float* __restrict__ wv,
    const float* __restrict__ wfc,
    const float* __restrict__ gln, const float* __restrict__ bln)
{
    extern __shared__ float sm[];
    float* sA  = sm + OFF_A;
    float* sQp = sm + OFF_Q;
    float* sKp = sm + OFF_K;
    float* sVp = sm + OFF_V;
    float* sP  = sm + OFF_P;
    float* sO  = sm + OFF_O;
    float* sF  = sm + OFF_F;
    float* sMu = sm + OFF_MU;
    float* sRs = sm + OFF_RS;

    int tid = threadIdx.x;
    int w = tid >> 5;
    int lane = tid & 31;

    size_t base = (size_t)blockIdx.x * 2048;
    for (int idx = tid; idx < 2048; idx += 512) sA[idx] = g_aw[base + idx];
    __syncthreads();

    // ---- QKV projections (weights direct from wq/wk/wv) ----
    {
        int r0 = w * 2, r1 = r0 + 1;
        int cl = lane * 4;
        int h = cl >> 5, within = cl & 31;
        const float* ar0 = sA + r0 * 64;
        const float* ar1 = sA + r1 * 64;
#pragma unroll
        for (int pass = 0; pass < 3; pass++) {
            const float* wsel = (pass == 0) ? wq : (pass == 1) ? wk : wv;
            u64 a0p[2] = {0ull, 0ull}, a1p[2] = {0ull, 0ull};
            const float* wp = wsel + cl;
#pragma unroll 4
            for (int k = 0; k < 64; k++) {
                ulonglong2 w4 = *(const ulonglong2*)&wp[k * 128];
                u64 a0 = bc2(ar0[k]), a1 = bc2(ar1[k]);
                fma2(a0p[0], a0, w4.x); fma2(a0p[1], a0, w4.y);
                fma2(a1p[0], a1, w4.x); fma2(a1p[1], a1, w4.y);
            }
            float2 q001 = up2(a0p[0]), q023 = up2(a0p[1]);
            float2 q101 = up2(a1p[0]), q123 = up2(a1p[1]);
            if (pass < 2) {
                float* dst = (pass == 0) ? sQp : sKp;
                int pc = h * 33 + within;
                dst[r0 * QPS + pc]     = q001.x; dst[r0 * QPS + pc + 1] = q001.y;
                dst[r0 * QPS + pc + 2] = q023.x; dst[r0 * QPS + pc + 3] = q023.y;
                dst[r1 * QPS + pc]     = q101.x; dst[r1 * QPS + pc + 1] = q101.y;
                dst[r1 * QPS + pc + 2] = q123.x; dst[r1 * QPS + pc + 3] = q123.y;
            } else {
                int pc = h * 36 + within;
                *(float4*)&sVp[r0 * VPS + pc] = make_float4(q001.x, q001.y, q023.x, q023.y);
                *(float4*)&sVp[r1 * VPS + pc] = make_float4(q101.x, q101.y, q123.x, q123.y);
            }
        }
    }
    __syncthreads();

    // ---- scores + softmax ----
    {
        int b = w >> 2, h = w & 3;
        int s = lane & 7, dgrp = lane >> 3;
        const float* qb = sQp + (b * 8 + s) * QPS + h * 33 + dgrp * 8;
        float q[8];
#pragma unroll
        for (int d = 0; d < 8; d++) q[d] = qb[d];
        float scv[8];
#pragma unroll
        for (int u = 0; u < 8; u++) {
            const float* kr = sKp + (b * 8 + u) * QPS + h * 33 + dgrp * 8;
            float p = 0.f;
#pragma unroll
            for (int d = 0; d < 8; d++) p += q[d] * kr[d];
            scv[u] = p;
        }
#pragma unroll
        for (int u = 0; u < 8; u++) {
            scv[u] += __shfl_xor_sync(0xffffffffu, scv[u], 8);
            scv[u] += __shfl_xor_sync(0xffffffffu, scv[u], 16);
        }
        if (lane < 8) {
            float mx = -1e30f;
#pragma unroll
            for (int u = 0; u < 8; u++) {
                scv[u] *= 0.17677669529663687f;
                mx = fmaxf(mx, scv[u]);
            }
            float sum = 0.f;
#pragma unroll
            for (int u = 0; u < 8; u++) { scv[u] = __expf(scv[u] - mx); sum += scv[u]; }
            float inv = 1.f / sum;
            float* pr = sP + ((b * 4 + h) * 8 + s) * 9;
#pragma unroll
            for (int u = 0; u < 8; u++) pr[u] = scv[u] * inv;
        }
    }
    __syncthreads();

    // ---- O = P @ V ----
    {
        int b = w >> 2;
        int s0 = (w & 3) * 2, s1 = s0 + 1;
        int c0 = lane * 4;
        int h = c0 >> 5;
        int pc = h * 36 + (c0 & 31);
        float o0[4], o1[4];
#pragma unroll
        for (int t = 0; t < 4; t++) { o0[t] = 0.f; o1[t] = 0.f; }
#pragma unroll
        for (int u = 0; u < 8; u++) {
            float4 v4 = *(const float4*)&sVp[(b * 8 + u) * VPS + pc];
            float p0 = sP[((b * 4 + h) * 8 + s0) * 9 + u];
            float p1 = sP[((b * 4 + h) * 8 + s1) * 9 + u];
            o0[0] += p0 * v4.x; o0[1] += p0 * v4.y; o0[2] += p0 * v4.z; o0[3] += p0 * v4.w;
            o1[0] += p1 * v4.x; o1[1] += p1 * v4.y; o1[2] += p1 * v4.z; o1[3] += p1 * v4.w;
        }
        *(float4*)&sO[(b * 8 + s0) * OPS + c0] = make_float4(o0[0], o0[1], o0[2], o0[3]);
        *(float4*)&sO[(b * 8 + s1) * OPS + c0] = make_float4(o1[0], o1[1], o1[2], o1[3]);
    }
    __syncthreads();

    // ---- fc + residual ----
    {
        int r0 = w * 2, r1 = r0 + 1;
        int c0 = lane * 2;
        u64 p0 = 0ull, p1 = 0ull;
        const float* o0 = sO + r0 * OPS;
        const float* o1 = sO + r1 * OPS;
#pragma unroll 4
        for (int k = 0; k < 128; k++) {
            u64 w2 = *(const u64*)&wfc[k * 64 + c0];
            fma2(p0, bc2(o0[k]), w2);
            fma2(p1, bc2(o1[k]), w2);
        }
        float2 f0 = up2(p0), f1 = up2(p1);
        sF[r0 * FPS + c0]     = f0.x + sA[r0 * 64 + c0];
        sF[r0 * FPS + c0 + 1] = f0.y + sA[r0 * 64 + c0 + 1];
        sF[r1 * FPS + c0]     = f1.x + sA[r1 * 64 + c0];
        sF[r1 * FPS + c0 + 1] = f1.y + sA[r1 * 64 + c0 + 1];
    }
    __syncthreads();

    if (tid < 32) {
        const float* fr = sF + tid * FPS;
        float m = 0.f;
#pragma unroll
        for (int c = 0; c < 64; c++) m += fr[c];
        m *= (1.f / 64.f);
        float v = 0.f;
#pragma unroll
        for (int c = 0; c < 64; c++) { float d = fr[c] - m; v += d * d; }
        v *= (1.f / 64.f);
        sMu[tid] = m;
        sRs[tid] = rsqrtf(v + 1e-6f);
    }
    __syncthreads();

    for (int idx = tid; idx < 2048; idx += 512) {
        int r = idx >> 6, c = idx & 63;
        g_att[base + idx] = (sF[r * FPS + c] - sMu[r]) * sRs[r] * gln[c] + bln[c];
    }
}

// ---------------- kernel F: L/R GEMMs + column stats ----------------
__global__ void k_LR(const float* __restrict__ hsrc, const float* __restrict__ Win1)
{
    __shared__ float sHT[64][34];
    int tid = threadIdx.x;
    int row0 = blockIdx.x * 32;
    for (int idx = tid; idx < 32 * 64; idx += 256) {
        int r = idx / 64, k = idx % 64;
        sHT[k][r] = hsrc[(row0 + r) * 64 + k];
    }
    __syncthreads();
    int cc = tid;
    int cm = cc & 127;
    u64 acc2[16];
#pragma unroll
    for (int t = 0; t < 16; t++) acc2[t] = 0ull;
    for (int k = 0; k < 64; k++) {
        float w = (cc < 128) ? Win1[k * 128 + cm] : Win1[(64 + k) * 128 + cm];
        u64 w2 = bc2(w);
#pragma unroll
        for (int t = 0; t < 16; t++)
            fma2(acc2[t], lds2(&sHT[k][2 * t]), w2);
    }
    float* dst = (cc < 128) ? g_L : g_R;
    float s = 0.f, q = 0.f;
#pragma unroll
    for (int t = 0; t < 16; t++) {
        float2 v2 = up2(acc2[t]);
        dst[(row0 + 2 * t) * 128 + cm] = v2.x;
        dst[(row0 + 2 * t + 1) * 128 + cm] = v2.y;
        s += v2.x + v2.y; q += v2.x * v2.x + v2.y * v2.y;
    }
    atomicAdd(&g_in_acc[cc], s);
    atomicAdd(&g_in_acc[256 + cc], q);
}

__global__ void k_cross() {
    __shared__ float sred[256];
    int tid = threadIdx.x;
    int c = tid & 127;
    int bg = tid >> 7;
    int b0 = blockIdx.x * 32;
    float cr = 0.f;
    for (int bb = bg * 16; bb < bg * 16 + 16; bb++) {
        int b = b0 + bb;
        float sl = 0.f, sr = 0.f;
#pragma unroll
        for (int i = 0; i < 8; i++) {
            sl += g_L[(b * 8 + i) * 128 + c];
            sr += g_R[(b * 8 + i) * 128 + c];
        }
        cr += sl * sr;
    }
    sred[tid] = cr; __syncthreads();
    if (tid < 128) atomicAdd(&g_in_acc[512 + tid], sred[tid] + sred[tid + 128]);
}

// ---------------- kernel I: infer GEMM + KLD (R12 form) ----------------
__global__ __launch_bounds__(256) void k_infer(
    const float* __restrict__ Win2, const float* __restrict__ bin2,
    const float* __restrict__ bin1,
    const float* __restrict__ gin, const float* __restrict__ bein,
    float* __restrict__ kld_out)
{
    __shared__ float sL[8 * 128], sR[8 * 128];
    __shared__ __align__(16) float sUT[128 * 36];
    __shared__ float sIP[32 * 128];
    __shared__ float s_sc[128], s_sh[128];
    __shared__ float sred[256];
    int b = blockIdx.x;
    int tid = threadIdx.x;
    for (int idx = tid; idx < 1024; idx += 256) {
        sL[idx] = g_L[(size_t)b * 1024 + idx];
        sR[idx] = g_R[(size_t)b * 1024 + idx];
    }
    if (tid < 128) {
        int c = tid;
        float sl = g_in_acc[c], sr = g_in_acc[128 + c];
        float ql = g_in_acc[256 + c], qr = g_in_acc[384 + c];
        float cr = g_in_acc[512 + c];
        float beta = bin1[c];
        const float Nr = 262144.f;
        float mean = 8.f * (sl + sr) / Nr + beta;
        float e2 = (8.f * ql + 8.f * qr + 2.f * cr + 16.f * beta * (sl + sr)) / Nr + beta * beta;
        float var = e2 - mean * mean;
        float s = rsqrtf(var + 1e-5f) * gin[c];
        s_sc[c] = s;
        s_sh[c] = bein[c] + (beta - mean) * s;
    }
    __syncthreads();

    int wr = tid >> 5;
    int cg = tid & 31;
    float4 bia = *(const float4*)&bin2[cg * 4];
    float kacc = 0.f;

    for (int half = 0; half < 2; half++) {
        int i0 = half * 4;
        for (int idx = tid; idx < 4096; idx += 256) {
            int r = idx >> 7, k = idx & 127;
            int ii = r >> 3, j = r & 7;
            float v = (sL[(i0 + ii) * 128 + k] + sR[j * 128 + k]) * s_sc[k] + s_sh[k];
            sUT[k * 36 + r] = v >= 0.f ? v : 0.01f * v;
        }
        __syncthreads();
        u64 acc2[4][2];
#pragma unroll
        for (int i = 0; i < 4; i++) { acc2[i][0] = 0ull; acc2[i][1] = 0ull; }
        for (int k = 0; k < 128; k++) {
            float4 a4 = *(const float4*)&sUT[k * 36 + wr * 4];
            ulonglong2 w = *(const ulonglong2*)&Win2[k * 128 + cg * 4];
            u64 b0 = bc2(a4.x), b1 = bc2(a4.y), b2 = bc2(a4.z), b3 = bc2(a4.w);
            fma2(acc2[0][0], b0, w.x); fma2(acc2[0][1], b0, w.y);
            fma2(acc2[1][0], b1, w.x); fma2(acc2[1][1], b1, w.y);
            fma2(acc2[2][0], b2, w.x); fma2(acc2[2][1], b2, w.y);
            fma2(acc2[3][0], b3, w.x); fma2(acc2[3][1], b3, w.y);
        }
#pragma unroll
        for (int i = 0; i < 4; i++) {
            float2 a01 = up2(acc2[i][0]), a23 = up2(acc2[i][1]);
            *(float4*)&sIP[(wr * 4 + i) * 128 + cg * 4] =
                make_float4(a01.x + bia.x, a01.y + bia.y, a23.x + bia.z, a23.y + bia.w);
        }
        __syncthreads();
        for (int ii = 0; ii < 4; ii++) {
            const float* mrow = g_mean + (size_t)(b * 8 + i0 + ii) * 512;
            const float* vrow = g_lvar + (size_t)(b * 8 + i0 + ii) * 512;
            for (int idx = tid; idx < 512; idx += 256) {
                int j = idx >> 6, d = idx & 63;
                float im  = sIP[(ii * 8 + j) * 128 + d];
                float liv = fmaxf(sIP[(ii * 8 + j) * 128 + 64 + d], LN0002);
                float riv = __expf(-liv);
                float lv  = vrow[idx];
                float v0  = __expf(lv);
                float dm  = mrow[idx] - im;
                kacc += 0.5f * (liv - lv) + 0.5f * (v0 + dm * dm) * riv - 0.5f;
            }
        }
        __syncthreads();
    }
    sred[tid] = kacc; __syncthreads();
    for (int s = 128; s > 0; s >>= 1) {
        if (tid < s) sred[tid] += sred[tid + s];
        __syncthreads();
    }
    if (tid == 0) kld_out[b] = sred[0] * (1.f / 4096.f);
}

// ---------------- kernel L: mlp2 ----------------
__global__ void k_mlp2(const float* __restrict__ hsrc,
                       const float* __restrict__ W2, const float* __restrict__ b2,
                       float* __restrict__ qout)
{
    __shared__ float sWt[14 * 576];
    int tid = threadIdx.x;
    for (int idx = tid; idx < 14 * 576; idx += 256) {
        int c = idx / 576, k = idx % 576;
        sWt[c * 576 + k] = W2[k * 14 + c];
    }
    __syncthreads();
    int w = tid >> 5, l = tid & 31;
    size_t row = (size_t)blockIdx.x * 8 + w;
    const float* hr = hsrc + row * 64;
    const float* ar = g_att + row * 512;
    float acc[14];
#pragma unroll
    for (int c = 0; c < 14; c++) acc[c] = 0.f;
    for (int k = l; k < 576; k += 32) {
        float v = (k < 64) ? hr[k] : ar[k - 64];
#pragma unroll
        for (int c = 0; c < 14; c++) acc[c] += v * sWt[c * 576 + k];
    }
#pragma unroll
    for (int c = 0; c < 14; c++) {
        float a = acc[c];
        for (int o = 16; o > 0; o >>= 1) a += __shfl_down_sync(0xffffffffu, a, o);
        if (l == 0) qout[row * 14 + c] = a + b2[c];
    }
}

// ---------------- launch ----------------
extern "C" void kernel_launch(void* const* d_in, const int* in_sizes, int n_in,
                              void* d_out, int out_size)
{
    const float* inputs = (const float*)d_in[0];
    const float* hidden = (const float*)d_in[1];
    const float* noise  = (const float*)d_in[2];
    const float* w_mlp1 = (const float*)d_in[3];
    const float* b_mlp1 = (const float*)d_in[4];
    const float* w_ih   = (const float*)d_in[5];
    const float* b_ih   = (const float*)d_in[6];
    const float* w_hh   = (const float*)d_in[7];
    const float* b_hh   = (const float*)d_in[8];
    const float* w_ae1  = (const float*)d_in[9];
    const float* b_ae1  = (const float*)d_in[10];
    const float* g_ae   = (const float*)d_in[11];
    const float* be_ae  = (const float*)d_in[12];
    const float* w_ae2  = (const float*)d_in[13];
    const float* b_ae2  = (const float*)d_in[14];
    const float* w_in1  = (const float*)d_in[15];
    const float* b_in1  = (const float*)d_in[16];
    const float* g_in   = (const float*)d_in[17];
    const float* be_in  = (const float*)d_in[18];
    const float* w_in2  = (const float*)d_in[19];
    const float* b_in2  = (const float*)d_in[20];
    const float* w_q    = (const float*)d_in[21];
    const float* w_k    = (const float*)d_in[22];
    const float* w_v    = (const float*)d_in[23];
    const float* w_fc   = (const float*)d_in[24];
    const float* g_ln   = (const float*)d_in[25];
    const float* b_ln   = (const float*)d_in[26];
    const float* w_mlp2 = (const float*)d_in[27];
    const float* b_mlp2 = (const float*)d_in[28];

    float* out = (float*)d_out;
    float* q_out   = out;
    float* h_out   = out + NROWS * NACT;
    float* kld_out = h_out + NROWS * Hdim;

    static int attn_smem_set = 0;
    const int ATTN_SMEM = ATTN_SMEM_FLOATS * 4;
    if (!attn_smem_set) {
        cudaFuncSetAttribute(k_attn, cudaFuncAttributeMaxDynamicSharedMemorySize, ATTN_SMEM);
        attn_smem_set = 1;
    }

    // launch index 3 (k_attn) is the ncu capture slot
    k_mlp1_gru<<<NROWS / 32, 512>>>(inputs, hidden, w_mlp1, b_mlp1, w_ih, b_ih, w_hh, b_hh, h_out);
    k_ae1<<<NROWS / 32, 256>>>(h_out, w_ae1, b_ae1);
    k_ae2<<<dim3(NROWS / 32, 4), 256>>>(w_ae2, b_ae2, noise, g_ae, be_ae);
    k_attn<<<NROWS / 4, 512, ATTN_SMEM>>>(w_q, w_k, w_v, w_fc, g_ln, b_ln);
    k_LR<<<NROWS / 32, 256>>>(h_out, w_in1);
    k_cross<<<BSZ / 32, 256>>>();
    k_infer<<<BSZ, 256>>>(w_in2, b_in2, b_in1, g_in, be_in, kld_out);
    k_mlp2<<<NROWS / 8, 256>>>(h_out, w_mlp2, b_mlp2, q_out);
}

// round 17
// speedup vs baseline: 1.2714x; 1.0435x over previous
#include <cuda_runtime.h>
#include <math.h>

#define NAg 8
#define Hdim 64
#define LATENT 512
#define NACT 14
#define BSZ 4096
#define NROWS 32768   // BSZ*NAg
#define LN0002 (-6.2146080984221914f)

typedef unsigned long long u64;

// ---- packed fp32x2 helpers ----
__device__ __forceinline__ u64 bc2(float x) {
    u64 r; asm("mov.b64 %0, {%1, %2};" : "=l"(r) : "f"(x), "f"(x)); return r;
}
__device__ __forceinline__ void fma2(u64& d, u64 a, u64 b) {
    asm("fma.rn.f32x2 %0, %1, %2, %3;" : "=l"(d) : "l"(a), "l"(b), "l"(d));
}
__device__ __forceinline__ float2 up2(u64 v) {
    float lo, hi; asm("mov.b64 {%0, %1}, %2;" : "=f"(lo), "=f"(hi) : "l"(v));
    return make_float2(lo, hi);
}
__device__ __forceinline__ u64 lds2(const float* p) { return *(const u64*)p; }
__device__ __forceinline__ float tanh_fast(float x) {
    float r; asm("tanh.approx.f32 %0, %1;" : "=f"(r) : "f"(x)); return r;
}
__device__ __forceinline__ float sigmoid_fast(float x) {
    return 1.f / (1.f + __expf(-x));
}

// ---------------- scratch ----------------
__device__ float g_uae[NROWS * 128];
__device__ float g_ae_acc[2 * 128];
__device__ float g_mean[NROWS * 512];
__device__ float g_lvar[NROWS * 512];
__device__ float g_aw[NROWS * 512];
__device__ float g_L[NROWS * 128];
__device__ float g_R[NROWS * 128];
__device__ float g_in_acc[5 * 128];
__device__ float g_att[NROWS * 512];

// ---------------- kernel A: fused mlp1 + GRU (+ accumulator zeroing) ----------------
__global__ __launch_bounds__(512) void k_mlp1_gru(
    const float* __restrict__ in, const float* __restrict__ hin,
    const float* __restrict__ W1, const float* __restrict__ b1,
    const float* __restrict__ Wih, const float* __restrict__ bih,
    const float* __restrict__ Whh, const float* __restrict__ bhh,
    float* __restrict__ hout)
{
    __shared__ float sInT[96][34];
    __shared__ float sXT[64][34];
    __shared__ float sHT[64][34];
    int tid = threadIdx.x;
    int row0 = blockIdx.x * 32;

    if (blockIdx.x == 0) {
        for (int i = tid; i < 256; i += 512) g_ae_acc[i] = 0.f;
        for (int i = tid; i < 640; i += 512) g_in_acc[i] = 0.f;
    }

    for (int idx = tid; idx < 32 * 96; idx += 512) {
        int r = idx / 96, k = idx % 96;
        sInT[k][r] = in[(row0 + r) * 96 + k];
    }
    for (int idx = tid; idx < 32 * 64; idx += 512) {
        int r = idx / 64, k = idx % 64;
        sHT[k][r] = hin[(row0 + r) * 64 + k];
    }
    __syncthreads();

    int c = tid & 63;
    int rg = tid >> 6;      // 0..7 -> rows rg*4..+3
    {
        u64 acc2[2] = {0ull, 0ull};
        for (int k = 0; k < 96; k++) {
            u64 w2 = bc2(W1[k * 64 + c]);
#pragma unroll
            for (int t = 0; t < 2; t++)
                fma2(acc2[t], lds2(&sInT[k][rg * 4 + 2 * t]), w2);
        }
        float b = b1[c];
#pragma unroll
        for (int t = 0; t < 2; t++) {
            float2 v = up2(acc2[t]);
            v.x += b; v.y += b;
            v.x = v.x > 0.f ? v.x : 0.f;
            v.y = v.y > 0.f ? v.y : 0.f;
            *(float2*)&sXT[c][rg * 4 + 2 * t] = v;
        }
    }
    __syncthreads();

    {
        int j = c;
        u64 axr2[2], axz2[2], axn2[2], ahr2[2], ahz2[2], ahn2[2];
#pragma unroll
        for (int t = 0; t < 2; t++) { axr2[t]=axz2[t]=axn2[t]=ahr2[t]=ahz2[t]=ahn2[t]=0ull; }
        for (int k = 0; k < 64; k++) {
            u64 wr = bc2(Wih[k * 192 + j]);
            u64 wz = bc2(Wih[k * 192 + 64 + j]);
            u64 wn = bc2(Wih[k * 192 + 128 + j]);
            u64 vr = bc2(Whh[k * 192 + j]);
            u64 vz = bc2(Whh[k * 192 + 64 + j]);
            u64 vn = bc2(Whh[k * 192 + 128 + j]);
#pragma unroll
            for (int t = 0; t < 2; t++) {
                u64 x2 = lds2(&sXT[k][rg * 4 + 2 * t]);
                u64 h2 = lds2(&sHT[k][rg * 4 + 2 * t]);
                fma2(axr2[t], x2, wr); fma2(axz2[t], x2, wz); fma2(axn2[t], x2, wn);
                fma2(ahr2[t], h2, vr); fma2(ahz2[t], h2, vz); fma2(ahn2[t], h2, vn);
            }
        }
        float br = bih[j], bz = bih[64 + j], bn_ = bih[128 + j];
        float cr = bhh[j], cz = bhh[64 + j], cn = bhh[128 + j];
#pragma unroll
        for (int t = 0; t < 2; t++) {
            float2 xr = up2(axr2[t]), xz = up2(axz2[t]), xn = up2(axn2[t]);
            float2 hr = up2(ahr2[t]), hz = up2(ahz2[t]), hn = up2(ahn2[t]);
#pragma unroll
            for (int lz = 0; lz < 2; lz++) {
                int r = rg * 4 + 2 * t + lz;
                float XR = lz ? xr.y : xr.x, XZ = lz ? xz.y : xz.x, XN = lz ? xn.y : xn.x;
                float HR = lz ? hr.y : hr.x, HZ = lz ? hz.y : hz.x, HN = lz ? hn.y : hn.x;
                float rg_ = sigmoid_fast((XR + br) + (HR + cr));
                float zg  = sigmoid_fast((XZ + bz) + (HZ + cz));
                float ng  = tanh_fast((XN + bn_) + rg_ * (HN + cn));
                float hprev = sHT[j][r];
                hout[(row0 + r) * 64 + j] = (1.f - zg) * ng + zg * hprev;
            }
        }
    }
}

// ---------------- kernel B: ae1 GEMM + column stats ----------------
__global__ void k_ae1(const float* __restrict__ hsrc,
                      const float* __restrict__ Wae1, const float* __restrict__ bae1)
{
    __shared__ float sHT[64][34];
    __shared__ float sred[256];
    int tid = threadIdx.x;
    int row0 = blockIdx.x * 32;
    for (int idx = tid; idx < 32 * 64; idx += 256) {
        int r = idx / 64, k = idx % 64;
        sHT[k][r] = hsrc[(row0 + r) * 64 + k];
    }
    __syncthreads();
    int c = tid & 127;
    int rg = tid >> 7;
    u64 acc2[8];
#pragma unroll
    for (int t = 0; t < 8; t++) acc2[t] = 0ull;
    for (int k = 0; k < 64; k++) {
        u64 w2 = bc2(Wae1[k * 128 + c]);
#pragma unroll
        for (int t = 0; t < 8; t++)
            fma2(acc2[t], lds2(&sHT[k][rg * 16 + 2 * t]), w2);
    }
    float b = bae1[c];
    float s = 0.f, q = 0.f;
#pragma unroll
    for (int t = 0; t < 8; t++) {
        float2 u2 = up2(acc2[t]);
        float u0 = u2.x + b, u1 = u2.y + b;
        g_uae[(row0 + rg * 16 + 2 * t) * 128 + c] = u0;
        g_uae[(row0 + rg * 16 + 2 * t + 1) * 128 + c] = u1;
        s += u0 + u1; q += u0 * u0 + u1 * u1;
    }
    sred[tid] = s; __syncthreads();
    if (tid < 128) atomicAdd(&g_ae_acc[tid], sred[tid] + sred[tid + 128]);
    __syncthreads();
    sred[tid] = q; __syncthreads();
    if (tid < 128) atomicAdd(&g_ae_acc[128 + tid], sred[tid] + sred[tid + 128]);
}

// ---------------- kernel D: ae2 GEMM (transposed sUT stride 34) ----------------
__global__ __launch_bounds__(256) void k_ae2(
    const float* __restrict__ Wae2, const float* __restrict__ bae2,
    const float* __restrict__ noise,
    const float* __restrict__ gae, const float* __restrict__ beae)
{
    __shared__ float sUT[128 * 34];
    __shared__ float s_sc[128], s_sh[128];
    int tid = threadIdx.x;
    int row0 = blockIdx.x * 32;
    int p = blockIdx.y;

    if (tid < 128) {
        float m = g_ae_acc[tid] * (1.f / 32768.f);
        float var = g_ae_acc[128 + tid] * (1.f / 32768.f) - m * m;
        float s = rsqrtf(var + 1e-5f) * gae[tid];
        s_sc[tid] = s;
        s_sh[tid] = beae[tid] - m * s;
    }
    __syncthreads();

    for (int idx = tid; idx < 32 * 128; idx += 256) {
        int r = idx >> 7, k = idx & 127;
        float u = g_uae[(size_t)row0 * 128 + idx];
        float v = u * s_sc[k] + s_sh[k];
        sUT[k * 34 + r] = v >= 0.f ? v : 0.01f * v;
    }
    __syncthreads();

    int rg = tid >> 5;
    int cg = tid & 31;
    int cm = p * 128 + cg * 4;
    int cv = 512 + cm;
    u64 acc2[2][8];
#pragma unroll
    for (int t = 0; t < 2; t++)
#pragma unroll
        for (int c = 0; c < 8; c++) acc2[t][c] = 0ull;

    for (int k = 0; k < 128; k++) {
        float4 wm = *(const float4*)&Wae2[k * 1024 + cm];
        float4 wv = *(const float4*)&Wae2[k * 1024 + cv];
        u64 wb[8];
        wb[0] = bc2(wm.x); wb[1] = bc2(wm.y); wb[2] = bc2(wm.z); wb[3] = bc2(wm.w);
        wb[4] = bc2(wv.x); wb[5] = bc2(wv.y); wb[6] = bc2(wv.z); wb[7] = bc2(wv.w);
#pragma unroll
        for (int t = 0; t < 2; t++) {
            u64 u2 = lds2(&sUT[k * 34 + rg * 4 + 2 * t]);
#pragma unroll
            for (int c = 0; c < 8; c++) fma2(acc2[t][c], u2, wb[c]);
        }
    }
    float4 bm = *(const float4*)&bae2[cm];
    float4 bv = *(const float4*)&bae2[cv];
#pragma unroll
    for (int t = 0; t < 2; t++) {
        float2 c0 = up2(acc2[t][0]), c1 = up2(acc2[t][1]);
        float2 c2 = up2(acc2[t][2]), c3 = up2(acc2[t][3]);
        float2 v0 = up2(acc2[t][4]), v1 = up2(acc2[t][5]);
        float2 v2 = up2(acc2[t][6]), v3 = up2(acc2[t][7]);
#pragma unroll
        for (int lz = 0; lz < 2; lz++) {
            size_t row = row0 + rg * 4 + 2 * t + lz;
            float m0 = (lz ? c0.y : c0.x) + bm.x;
            float m1 = (lz ? c1.y : c1.x) + bm.y;
            float m2 = (lz ? c2.y : c2.x) + bm.z;
            float m3 = (lz ? c3.y : c3.x) + bm.w;
            float l0 = fmaxf((lz ? v0.y : v0.x) + bv.x, LN0002);
            float l1 = fmaxf((lz ? v1.y : v1.x) + bv.y, LN0002);
            float l2 = fmaxf((lz ? v2.y : v2.x) + bv.z, LN0002);
            float l3 = fmaxf((lz ? v3.y : v3.x) + bv.w, LN0002);
            size_t off = row * 512 + cm;
            float4 nz = *(const float4*)&noise[off];
            *(float4*)&g_mean[off] = make_float4(m0, m1, m2, m3);
            *(float4*)&g_lvar[off] = make_float4(l0, l1, l2, l3);
            *(float4*)&g_aw[off]   = make_float4(m0 + __expf(0.5f * l0) * nz.x,
                                                 m1 + __expf(0.5f * l1) * nz.y,
                                                 m2 + __expf(0.5f * l2) * nz.z,
                                                 m3 + __expf(0.5f * l3) * nz.w);
        }
    }
}

// ---------------- kernel K: fused MHA + layernorm -> g_att (launch slot 3) ----------------
// occ fix (512,2). This round: float4 activation loads in QKV + fc loops
// (LDS instr/thread ~730 -> ~300; kernel was L1=83.6% bound).
#define QPS 133
#define VPS 144
#define OPS 132
#define FPS 67
#define OFF_A   0
#define OFF_Q   2048
#define OFF_K   6304
#define OFF_V   10560
#define OFF_P   15168
#define OFF_O   16320
#define OFF_F   20544
#define OFF_MU  22688
#define OFF_RS  22720
#define ATTN_SMEM_FLOATS 22752

__global__ __launch_bounds__(512, 2) void k_attn(
    const float* __restrict__ wq, const float* __restrict__ wk,
    const float* __restrict__ wv,
    const float* __restrict__ wfc,
    const float* __restrict__ gln, const float* __restrict__ bln)
{
    extern __shared__ float sm[];
    float* sA  = sm + OFF_A;
    float* sQp = sm + OFF_Q;
    float* sKp = sm + OFF_K;
    float* sVp = sm + OFF_V;
    float* sP  = sm + OFF_P;
    float* sO  = sm + OFF_O;
    float* sF  = sm + OFF_F;
    float* sMu = sm + OFF_MU;
    float* sRs = sm + OFF_RS;

    int tid = threadIdx.x;
    int w = tid >> 5;
    int lane = tid & 31;

    size_t base = (size_t)blockIdx.x * 2048;
    for (int idx = tid; idx < 2048; idx += 512) sA[idx] = g_aw[base + idx];
    __syncthreads();

    // ---- QKV projections: float4 row loads, k in groups of 4 ----
    {
        int r0 = w * 2, r1 = r0 + 1;
        int cl = lane * 4;
        int h = cl >> 5, within = cl & 31;
        const float* ar0 = sA + r0 * 64;
        const float* ar1 = sA + r1 * 64;
#pragma unroll
        for (int pass = 0; pass < 3; pass++) {
            const float* wsel = (pass == 0) ? wq : (pass == 1) ? wk : wv;
            u64 a0p[2] = {0ull, 0ull}, a1p[2] = {0ull, 0ull};
            const float* wp = wsel + cl;
            for (int kg = 0; kg < 16; kg++) {
                float a0f[4], a1f[4];
                *(float4*)a0f = *(const float4*)&ar0[kg * 4];
                *(float4*)a1f = *(const float4*)&ar1[kg * 4];
#pragma unroll
                for (int kk = 0; kk < 4; kk++) {
                    ulonglong2 w4 = *(const ulonglong2*)&wp[(kg * 4 + kk) * 128];
                    u64 a0 = bc2(a0f[kk]), a1 = bc2(a1f[kk]);
                    fma2(a0p[0], a0, w4.x); fma2(a0p[1], a0, w4.y);
                    fma2(a1p[0], a1, w4.x); fma2(a1p[1], a1, w4.y);
                }
            }
            float2 q001 = up2(a0p[0]), q023 = up2(a0p[1]);
            float2 q101 = up2(a1p[0]), q123 = up2(a1p[1]);
            if (pass < 2) {
                float* dst = (pass == 0) ? sQp : sKp;
                int pc = h * 33 + within;
                dst[r0 * QPS + pc]     = q001.x; dst[r0 * QPS + pc + 1] = q001.y;
                dst[r0 * QPS + pc + 2] = q023.x; dst[r0 * QPS + pc + 3] = q023.y;
                dst[r1 * QPS + pc]     = q101.x; dst[r1 * QPS + pc + 1] = q101.y;
                dst[r1 * QPS + pc + 2] = q123.x; dst[r1 * QPS + pc + 3] = q123.y;
            } else {
                int pc = h * 36 + within;
                *(float4*)&sVp[r0 * VPS + pc] = make_float4(q001.x, q001.y, q023.x, q023.y);
                *(float4*)&sVp[r1 * VPS + pc] = make_float4(q101.x, q101.y, q123.x, q123.y);
            }
        }
    }
    __syncthreads();

    // ---- scores + softmax ----
    {
        int b = w >> 2, h = w & 3;
        int s = lane & 7, dgrp = lane >> 3;
        const float* qb = sQp + (b * 8 + s) * QPS + h * 33 + dgrp * 8;
        float q[8];
#pragma unroll
        for (int d = 0; d < 8; d++) q[d] = qb[d];
        float scv[8];
#pragma unroll
        for (int u = 0; u < 8; u++) {
            const float* kr = sKp + (b * 8 + u) * QPS + h * 33 + dgrp * 8;
            float p = 0.f;
#pragma unroll
            for (int d = 0; d < 8; d++) p += q[d] * kr[d];
            scv[u] = p;
        }
#pragma unroll
        for (int u = 0; u < 8; u++) {
            scv[u] += __shfl_xor_sync(0xffffffffu, scv[u], 8);
            scv[u] += __shfl_xor_sync(0xffffffffu, scv[u], 16);
        }
        if (lane < 8) {
            float mx = -1e30f;
#pragma unroll
            for (int u = 0; u < 8; u++) {
                scv[u] *= 0.17677669529663687f;
                mx = fmaxf(mx, scv[u]);
            }
            float sum = 0.f;
#pragma unroll
            for (int u = 0; u < 8; u++) { scv[u] = __expf(scv[u] - mx); sum += scv[u]; }
            float inv = 1.f / sum;
            float* pr = sP + ((b * 4 + h) * 8 + s) * 9;
#pragma unroll
            for (int u = 0; u < 8; u++) pr[u] = scv[u] * inv;
        }
    }
    __syncthreads();

    // ---- O = P @ V ----
    {
        int b = w >> 2;
        int s0 = (w & 3) * 2, s1 = s0 + 1;
        int c0 = lane * 4;
        int h = c0 >> 5;
        int pc = h * 36 + (c0 & 31);
        float o0[4], o1[4];
#pragma unroll
        for (int t = 0; t < 4; t++) { o0[t] = 0.f; o1[t] = 0.f; }
#pragma unroll
        for (int u = 0; u < 8; u++) {
            float4 v4 = *(const float4*)&sVp[(b * 8 + u) * VPS + pc];
            float p0 = sP[((b * 4 + h) * 8 + s0) * 9 + u];
            float p1 = sP[((b * 4 + h) * 8 + s1) * 9 + u];
            o0[0] += p0 * v4.x; o0[1] += p0 * v4.y; o0[2] += p0 * v4.z; o0[3] += p0 * v4.w;
            o1[0] += p1 * v4.x; o1[1] += p1 * v4.y; o1[2] += p1 * v4.z; o1[3] += p1 * v4.w;
        }
        *(float4*)&sO[(b * 8 + s0) * OPS + c0] = make_float4(o0[0], o0[1], o0[2], o0[3]);
        *(float4*)&sO[(b * 8 + s1) * OPS + c0] = make_float4(o1[0], o1[1], o1[2], o1[3]);
    }
    __syncthreads();

    // ---- fc + residual: float4 row loads, k in groups of 4 ----
    {
        int r0 = w * 2, r1 = r0 + 1;
        int c0 = lane * 2;
        u64 p0 = 0ull, p1 = 0ull;
        const float* o0 = sO + r0 * OPS;
        const float* o1 = sO + r1 * OPS;
        for (int kg = 0; kg < 32; kg++) {
            float of0[4], of1[4];
            *(float4*)of0 = *(const float4*)&o0[kg * 4];
            *(float4*)of1 = *(const float4*)&o1[kg * 4];
#pragma unroll
            for (int kk = 0; kk < 4; kk++) {
                u64 w2 = *(const u64*)&wfc[(kg * 4 + kk) * 64 + c0];
                fma2(p0, bc2(of0[kk]), w2);
                fma2(p1, bc2(of1[kk]), w2);
            }
        }
        float2 f0 = up2(p0), f1 = up2(p1);
        sF[r0 * FPS + c0]     = f0.x + sA[r0 * 64 + c0];
        sF[r0 * FPS + c0 + 1] = f0.y + sA[r0 * 64 + c0 + 1];
        sF[r1 * FPS + c0]     = f1.x + sA[r1 * 64 + c0];
        sF[r1 * FPS + c0 + 1] = f1.y + sA[r1 * 64 + c0 + 1];
    }
    __syncthreads();

    if (tid < 32) {
        const float* fr = sF + tid * FPS;
        float m = 0.f;
#pragma unroll
        for (int c = 0; c < 64; c++) m += fr[c];
        m *= (1.f / 64.f);
        float v = 0.f;
#pragma unroll
        for (int c = 0; c < 64; c++) { float d = fr[c] - m; v += d * d; }
        v *= (1.f / 64.f);
        sMu[tid] = m;
        sRs[tid] = rsqrtf(v + 1e-6f);
    }
    __syncthreads();

    for (int idx = tid; idx < 2048; idx += 512) {
        int r = idx >> 6, c = idx & 63;
        g_att[base + idx] = (sF[r * FPS + c] - sMu[r]) * sRs[r] * gln[c] + bln[c];
    }
}

// ---------------- kernel F: L/R GEMMs + column stats ----------------
__global__ void k_LR(const float* __restrict__ hsrc, const float* __restrict__ Win1)
{
    __shared__ float sHT[64][34];
    int tid = threadIdx.x;
    int row0 = blockIdx.x * 32;
    for (int idx = tid; idx < 32 * 64; idx += 256) {
        int r = idx / 64, k = idx % 64;
        sHT[k][r] = hsrc[(row0 + r) * 64 + k];
    }
    __syncthreads();
    int cc = tid;
    int cm = cc & 127;
    u64 acc2[16];
#pragma unroll
    for (int t = 0; t < 16; t++) acc2[t] = 0ull;
    for (int k = 0; k < 64; k++) {
        float w = (cc < 128) ? Win1[k * 128 + cm] : Win1[(64 + k) * 128 + cm];
        u64 w2 = bc2(w);
#pragma unroll
        for (int t = 0; t < 16; t++)
            fma2(acc2[t], lds2(&sHT[k][2 * t]), w2);
    }
    float* dst = (cc < 128) ? g_L : g_R;
    float s = 0.f, q = 0.f;
#pragma unroll
    for (int t = 0; t < 16; t++) {
        float2 v2 = up2(acc2[t]);
        dst[(row0 + 2 * t) * 128 + cm] = v2.x;
        dst[(row0 + 2 * t + 1) * 128 + cm] = v2.y;
        s += v2.x + v2.y; q += v2.x * v2.x + v2.y * v2.y;
    }
    atomicAdd(&g_in_acc[cc], s);
    atomicAdd(&g_in_acc[256 + cc], q);
}

__global__ void k_cross() {
    __shared__ float sred[256];
    int tid = threadIdx.x;
    int c = tid & 127;
    int bg = tid >> 7;
    int b0 = blockIdx.x * 32;
    float cr = 0.f;
    for (int bb = bg * 16; bb < bg * 16 + 16; bb++) {
        int b = b0 + bb;
        float sl = 0.f, sr = 0.f;
#pragma unroll
        for (int i = 0; i < 8; i++) {
            sl += g_L[(b * 8 + i) * 128 + c];
            sr += g_R[(b * 8 + i) * 128 + c];
        }
        cr += sl * sr;
    }
    sred[tid] = cr; __syncthreads();
    if (tid < 128) atomicAdd(&g_in_acc[512 + tid], sred[tid] + sred[tid + 128]);
}

// ---------------- kernel I: infer GEMM + KLD ----------------
__global__ __launch_bounds__(256) void k_infer(
    const float* __restrict__ Win2, const float* __restrict__ bin2,
    const float* __restrict__ bin1,
    const float* __restrict__ gin, const float* __restrict__ bein,
    float* __restrict__ kld_out)
{
    __shared__ float sL[8 * 128], sR[8 * 128];
    __shared__ __align__(16) float sUT[128 * 36];
    __shared__ float sIP[32 * 128];
    __shared__ float s_sc[128], s_sh[128];
    __shared__ float sred[256];
    int b = blockIdx.x;
    int tid = threadIdx.x;
    for (int idx = tid; idx < 1024; idx += 256) {
        sL[idx] = g_L[(size_t)b * 1024 + idx];
        sR[idx] = g_R[(size_t)b * 1024 + idx];
    }
    if (tid < 128) {
        int c = tid;
        float sl = g_in_acc[c], sr = g_in_acc[128 + c];
        float ql = g_in_acc[256 + c], qr = g_in_acc[384 + c];
        float cr = g_in_acc[512 + c];
        float beta = bin1[c];
        const float Nr = 262144.f;
        float mean = 8.f * (sl + sr) / Nr + beta;
        float e2 = (8.f * ql + 8.f * qr + 2.f * cr + 16.f * beta * (sl + sr)) / Nr + beta * beta;
        float var = e2 - mean * mean;
        float s = rsqrtf(var + 1e-5f) * gin[c];
        s_sc[c] = s;
        s_sh[c] = bein[c] + (beta - mean) * s;
    }
    __syncthreads();

    int wr = tid >> 5;
    int cg = tid & 31;
    float4 bia = *(const float4*)&bin2[cg * 4];
    float kacc = 0.f;

    for (int half = 0; half < 2; half++) {
        int i0 = half * 4;
        for (int idx = tid; idx < 4096; idx += 256) {
            int r = idx >> 7, k = idx & 127;
            int ii = r >> 3, j = r & 7;
            float v = (sL[(i0 + ii) * 128 + k] + sR[j * 128 + k]) * s_sc[k] + s_sh[k];
            sUT[k * 36 + r] = v >= 0.f ? v : 0.01f * v;
        }
        __syncthreads();
        u64 acc2[4][2];
#pragma unroll
        for (int i = 0; i < 4; i++) { acc2[i][0] = 0ull; acc2[i][1] = 0ull; }
        for (int k = 0; k < 128; k++) {
            float4 a4 = *(const float4*)&sUT[k * 36 + wr * 4];
            ulonglong2 w = *(const ulonglong2*)&Win2[k * 128 + cg * 4];
            u64 b0 = bc2(a4.x), b1 = bc2(a4.y), b2 = bc2(a4.z), b3 = bc2(a4.w);
            fma2(acc2[0][0], b0, w.x); fma2(acc2[0][1], b0, w.y);
            fma2(acc2[1][0], b1, w.x); fma2(acc2[1][1], b1, w.y);
            fma2(acc2[2][0], b2, w.x); fma2(acc2[2][1], b2, w.y);
            fma2(acc2[3][0], b3, w.x); fma2(acc2[3][1], b3, w.y);
        }
#pragma unroll
        for (int i = 0; i < 4; i++) {
            float2 a01 = up2(acc2[i][0]), a23 = up2(acc2[i][1]);
            *(float4*)&sIP[(wr * 4 + i) * 128 + cg * 4] =
                make_float4(a01.x + bia.x, a01.y + bia.y, a23.x + bia.z, a23.y + bia.w);
        }
        __syncthreads();
        for (int ii = 0; ii < 4; ii++) {
            const float* mrow = g_mean + (size_t)(b * 8 + i0 + ii) * 512;
            const float* vrow = g_lvar + (size_t)(b * 8 + i0 + ii) * 512;
            for (int idx = tid; idx < 512; idx += 256) {
                int j = idx >> 6, d = idx & 63;
                float im  = sIP[(ii * 8 + j) * 128 + d];
                float liv = fmaxf(sIP[(ii * 8 + j) * 128 + 64 + d], LN0002);
                float riv = __expf(-liv);
                float lv  = vrow[idx];
                float v0  = __expf(lv);
                float dm  = mrow[idx] - im;
                kacc += 0.5f * (liv - lv) + 0.5f * (v0 + dm * dm) * riv - 0.5f;
            }
        }
        __syncthreads();
    }
    sred[tid] = kacc; __syncthreads();
    for (int s = 128; s > 0; s >>= 1) {
        if (tid < s) sred[tid] += sred[tid + s];
        __syncthreads();
    }
    if (tid == 0) kld_out[b] = sred[0] * (1.f / 4096.f);
}

// ---------------- kernel L: mlp2 ----------------
__global__ void k_mlp2(const float* __restrict__ hsrc,
                       const float* __restrict__ W2, const float* __restrict__ b2,
                       float* __restrict__ qout)
{
    __shared__ float sWt[14 * 576];
    int tid = threadIdx.x;
    for (int idx = tid; idx < 14 * 576; idx += 256) {
        int c = idx / 576, k = idx % 576;
        sWt[c * 576 + k] = W2[k * 14 + c];
    }
    __syncthreads();
    int w = tid >> 5, l = tid & 31;
    size_t row = (size_t)blockIdx.x * 8 + w;
    const float* hr = hsrc + row * 64;
    const float* ar = g_att + row * 512;
    float acc[14];
#pragma unroll
    for (int c = 0; c < 14; c++) acc[c] = 0.f;
    for (int k = l; k < 576; k += 32) {
        float v = (k < 64) ? hr[k] : ar[k - 64];
#pragma unroll
        for (int c = 0; c < 14; c++) acc[c] += v * sWt[c * 576 + k];
    }
#pragma unroll
    for (int c = 0; c < 14; c++) {
        float a = acc[c];
        for (int o = 16; o > 0; o >>= 1) a += __shfl_down_sync(0xffffffffu, a, o);
        if (l == 0) qout[row * 14 + c] = a + b2[c];
    }
}

// ---------------- launch ----------------
extern "C" void kernel_launch(void* const* d_in, const int* in_sizes, int n_in,
                              void* d_out, int out_size)
{
    const float* inputs = (const float*)d_in[0];
    const float* hidden = (const float*)d_in[1];
    const float* noise  = (const float*)d_in[2];
    const float* w_mlp1 = (const float*)d_in[3];
    const float* b_mlp1 = (const float*)d_in[4];
    const float* w_ih   = (const float*)d_in[5];
    const float* b_ih   = (const float*)d_in[6];
    const float* w_hh   = (const float*)d_in[7];
    const float* b_hh   = (const float*)d_in[8];
    const float* w_ae1  = (const float*)d_in[9];
    const float* b_ae1  = (const float*)d_in[10];
    const float* g_ae   = (const float*)d_in[11];
    const float* be_ae  = (const float*)d_in[12];
    const float* w_ae2  = (const float*)d_in[13];
    const float* b_ae2  = (const float*)d_in[14];
    const float* w_in1  = (const float*)d_in[15];
    const float* b_in1  = (const float*)d_in[16];
    const float* g_in   = (const float*)d_in[17];
    const float* be_in  = (const float*)d_in[18];
    const float* w_in2  = (const float*)d_in[19];
    const float* b_in2  = (const float*)d_in[20];
    const float* w_q    = (const float*)d_in[21];
    const float* w_k    = (const float*)d_in[22];
    const float* w_v    = (const float*)d_in[23];
    const float* w_fc   = (const float*)d_in[24];
    const float* g_ln   = (const float*)d_in[25];
    const float* b_ln   = (const float*)d_in[26];
    const float* w_mlp2 = (const float*)d_in[27];
    const float* b_mlp2 = (const float*)d_in[28];

    float* out = (float*)d_out;
    float* q_out   = out;
    float* h_out   = out + NROWS * NACT;
    float* kld_out = h_out + NROWS * Hdim;

    static int attn_smem_set = 0;
    const int ATTN_SMEM = ATTN_SMEM_FLOATS * 4;
    if (!attn_smem_set) {
        cudaFuncSetAttribute(k_attn, cudaFuncAttributeMaxDynamicSharedMemorySize, ATTN_SMEM);
        attn_smem_set = 1;
    }

    // launch index 3 (k_attn) is the ncu capture slot
    k_mlp1_gru<<<NROWS / 32, 512>>>(inputs, hidden, w_mlp1, b_mlp1, w_ih, b_ih, w_hh, b_hh, h_out);
    k_ae1<<<NROWS / 32, 256>>>(h_out, w_ae1, b_ae1);
    k_ae2<<<dim3(NROWS / 32, 4), 256>>>(w_ae2, b_ae2, noise, g_ae, be_ae);
    k_attn<<<NROWS / 4, 512, ATTN_SMEM>>>(w_q, w_k, w_v, w_fc, g_ln, b_ln);
    k_LR<<<NROWS / 32, 256>>>(h_out, w_in1);
    k_cross<<<BSZ / 32, 256>>>();
    k_infer<<<BSZ, 256>>>(w_in2, b_in2, b_in1, g_in, be_in, kld_out);
    k_mlp2<<<NROWS / 8, 256>>>(h_out, w_mlp2, b_mlp2, q_out);
}